// round 1
// baseline (speedup 1.0000x reference)
#include <cuda_runtime.h>
#include <cstdint>
#include <math.h>

// Problem constants
#define BATCH 8192
#define RROLE 6
#define DDIM 1024
#define HDIM 256
#define MROWS (BATCH * RROLE)          // 49152
#define TEMP_INV 2.0f                   // 1/TEMP, TEMP=0.5
#define SINKHORN_ITERS 5

// Output layout (flattened tuple: answer, mapping, mapped_src, confidence)
#define OUT_ANSWER_OFF  0
#define OUT_MAPPING_OFF ((size_t)MROWS * DDIM)                         // 50331648
#define OUT_MAPPED_OFF  (OUT_MAPPING_OFF + (size_t)BATCH * RROLE * RROLE)
#define OUT_CONF_OFF    (OUT_MAPPED_OFF + (size_t)MROWS * HDIM)

// ------------------- device scratch (no allocations allowed) -------------------
__device__ float g_Wf[HDIM * 2 * HDIM];            // 256x512 fused W2@Wc
__device__ float g_x1[(size_t)MROWS * HDIM];       // post layer1 + rmsnorm
__device__ float g_ab[(size_t)MROWS * 2 * HDIM];   // gate proj / swiglu hidden
__device__ float g_bb[(size_t)MROWS * 2 * HDIM];   // value proj
__device__ float g_enc_src[(size_t)MROWS * HDIM];
__device__ float g_enc_tgt[(size_t)MROWS * HDIM];
__device__ float g_u[(size_t)MROWS * HDIM];        // enc_src @ Wbil
__device__ float g_comb[(size_t)MROWS * 2 * HDIM]; // [mapped_src, tgt_enc]

// ------------------- activations -------------------
__device__ __forceinline__ float gelu_tanh(float x) {
    float x3 = x * x * x;
    return 0.5f * x * (1.0f + tanhf(0.7978845608028654f * (x + 0.044715f * x3)));
}

// ------------------- generic tiled GEMM: C = act(A @ op(B) + bias) -------------------
// A: [M,K] row-major. If !TRANSB: B is [N,K] row-major (PyTorch/JAX Linear weight,
// computes A@B^T). If TRANSB: B is [K,N] row-major (computes A@B).
// BM=BN=64, BK=16, 256 threads, 4x4 microtile. Requires M%64==0, N%64==0, K%16==0.
template <bool TRANSB, int ACT>
__global__ __launch_bounds__(256) void gemm64_kernel(
    const float* __restrict__ A, const float* __restrict__ B,
    const float* __restrict__ bias, float* __restrict__ C,
    int M, int N, int K)
{
    __shared__ float As[16][64];
    __shared__ float Bs[16][64];

    const int bm = blockIdx.y * 64;
    const int bn = blockIdx.x * 64;
    const int tid = threadIdx.x;
    const int tx = tid & 15;       // 0..15 -> n
    const int ty = tid >> 4;       // 0..15 -> m

    // load indices
    const int arow = tid >> 2;            // 0..63
    const int akg  = (tid & 3) * 4;       // 0,4,8,12
    const int brow = tid >> 4;            // 0..15 (TRANSB)
    const int bng  = (tid & 15) * 4;      // 0..60 (TRANSB)

    float acc[4][4];
#pragma unroll
    for (int i = 0; i < 4; i++)
#pragma unroll
        for (int j = 0; j < 4; j++) acc[i][j] = 0.0f;

    for (int k0 = 0; k0 < K; k0 += 16) {
        // A tile -> As[k][m]
        float4 av = *(const float4*)(A + (size_t)(bm + arow) * K + k0 + akg);
        As[akg + 0][arow] = av.x;
        As[akg + 1][arow] = av.y;
        As[akg + 2][arow] = av.z;
        As[akg + 3][arow] = av.w;

        if (!TRANSB) {
            float4 bv = *(const float4*)(B + (size_t)(bn + arow) * K + k0 + akg);
            Bs[akg + 0][arow] = bv.x;
            Bs[akg + 1][arow] = bv.y;
            Bs[akg + 2][arow] = bv.z;
            Bs[akg + 3][arow] = bv.w;
        } else {
            float4 bv = *(const float4*)(B + (size_t)(k0 + brow) * N + bn + bng);
            *(float4*)&Bs[brow][bng] = bv;
        }
        __syncthreads();

#pragma unroll
        for (int k = 0; k < 16; k++) {
            float4 a4 = *(const float4*)&As[k][ty * 4];
            float4 b4 = *(const float4*)&Bs[k][tx * 4];
            acc[0][0] += a4.x * b4.x; acc[0][1] += a4.x * b4.y;
            acc[0][2] += a4.x * b4.z; acc[0][3] += a4.x * b4.w;
            acc[1][0] += a4.y * b4.x; acc[1][1] += a4.y * b4.y;
            acc[1][2] += a4.y * b4.z; acc[1][3] += a4.y * b4.w;
            acc[2][0] += a4.z * b4.x; acc[2][1] += a4.z * b4.y;
            acc[2][2] += a4.z * b4.z; acc[2][3] += a4.z * b4.w;
            acc[3][0] += a4.w * b4.x; acc[3][1] += a4.w * b4.y;
            acc[3][2] += a4.w * b4.z; acc[3][3] += a4.w * b4.w;
        }
        __syncthreads();
    }

    float4 bv = make_float4(0.f, 0.f, 0.f, 0.f);
    if (bias) bv = *(const float4*)(bias + bn + tx * 4);

#pragma unroll
    for (int i = 0; i < 4; i++) {
        float4 o;
        o.x = acc[i][0] + bv.x;
        o.y = acc[i][1] + bv.y;
        o.z = acc[i][2] + bv.z;
        o.w = acc[i][3] + bv.w;
        if (ACT == 1) {
            o.x = gelu_tanh(o.x); o.y = gelu_tanh(o.y);
            o.z = gelu_tanh(o.z); o.w = gelu_tanh(o.w);
        }
        *(float4*)(C + (size_t)(bm + ty * 4 + i) * N + bn + tx * 4) = o;
    }
}

// ------------------- rmsnorm (in-place): x = x * rsqrt(mean(x^2)+1e-6) * g -------------------
template <int NC>
__global__ void rmsnorm_kernel(float* __restrict__ x, const float* __restrict__ g, int rows)
{
    int row = blockIdx.x * 8 + (threadIdx.x >> 5);
    int lane = threadIdx.x & 31;
    if (row >= rows) return;
    float* p = x + (size_t)row * NC;
    constexpr int V = NC / 32;
    float v[V];
    float ss = 0.0f;
#pragma unroll
    for (int i = 0; i < V; i++) { v[i] = p[lane + 32 * i]; ss += v[i] * v[i]; }
#pragma unroll
    for (int o = 16; o > 0; o >>= 1) ss += __shfl_xor_sync(0xffffffffu, ss, o);
    float sc = rsqrtf(ss * (1.0f / NC) + 1e-6f);
#pragma unroll
    for (int i = 0; i < V; i++) p[lane + 32 * i] = v[i] * sc * g[lane + 32 * i];
}

// ------------------- swiglu combine: a = silu(a) * b (elementwise, float4) -------------------
__global__ void swiglu_kernel(float4* __restrict__ a, const float4* __restrict__ b, int n4)
{
    int i = blockIdx.x * blockDim.x + threadIdx.x;
    if (i >= n4) return;
    float4 x = a[i];
    float4 y = b[i];
    x.x = x.x / (1.0f + expf(-x.x)) * y.x;
    x.y = x.y / (1.0f + expf(-x.y)) * y.y;
    x.z = x.z / (1.0f + expf(-x.z)) * y.z;
    x.w = x.w / (1.0f + expf(-x.w)) * y.w;
    a[i] = x;
}

// ------------------- fused weight: Wf[256,512] = W2[256,256] @ Wc[256,512] -------------------
__global__ void fusew_kernel(const float* __restrict__ W2, const float* __restrict__ Wc,
                             float* __restrict__ Wf)
{
    int idx = blockIdx.x * blockDim.x + threadIdx.x;   // 131072 threads
    int i = idx >> 9;
    int j = idx & 511;
    float s = 0.0f;
    for (int k = 0; k < 256; k++) s += W2[i * 256 + k] * Wc[k * 512 + j];
    Wf[idx] = s;
}

// ------------------- per-batch: scores, sinkhorn, mapping, mapped_src, confidence, combined ---
__global__ __launch_bounds__(256) void batch_kernel(
    const float* __restrict__ u,        // [B*R, H] = enc_src @ Wbil
    const float* __restrict__ tgt,      // [B*R, H]
    const float* __restrict__ src,      // [B*R, H]
    const float* __restrict__ bbil,
    const float* __restrict__ Wc1, const float* __restrict__ bc1,
    float* __restrict__ out_mapping,    // [B, R, R]
    float* __restrict__ out_mapped,     // [B, R, H]
    float* __restrict__ out_conf,       // [B]
    float* __restrict__ combined)       // [B*R, 2H]
{
    const int b = blockIdx.x;
    const int tid = threadIdx.x;
    __shared__ float u_s[RROLE * HDIM];
    __shared__ float t_s[RROLE * HDIM];
    __shared__ float s_s[RROLE * HDIM];
    __shared__ float la[RROLE * RROLE];
    __shared__ float map_s[RROLE * RROLE];
    __shared__ float lse[RROLE];
    __shared__ float red[256];

    const size_t base = (size_t)b * RROLE * HDIM;
    for (int e = tid; e < RROLE * HDIM; e += 256) {
        u_s[e] = u[base + e];
        t_s[e] = tgt[base + e];
        s_s[e] = src[base + e];
    }
    __syncthreads();

    // log_alpha[i][j] = (u[i] . tgt[j] + bbil) / TEMP
    const float bb = bbil[0];
    const int warp = tid >> 5, lane = tid & 31;
    for (int p = warp; p < RROLE * RROLE; p += 8) {
        int i = p / RROLE, j = p % RROLE;
        float d = 0.0f;
        for (int h = lane; h < HDIM; h += 32) d += u_s[i * HDIM + h] * t_s[j * HDIM + h];
#pragma unroll
        for (int o = 16; o > 0; o >>= 1) d += __shfl_xor_sync(0xffffffffu, d, o);
        if (lane == 0) la[p] = (d + bb) * TEMP_INV;
    }
    __syncthreads();

    // Sinkhorn: row-normalize (over j), then col-normalize (over i), x5
    for (int it = 0; it < SINKHORN_ITERS; it++) {
        if (tid < RROLE) {
            float m = -1e30f;
            for (int j = 0; j < RROLE; j++) m = fmaxf(m, la[tid * RROLE + j]);
            float s = 0.0f;
            for (int j = 0; j < RROLE; j++) s += expf(la[tid * RROLE + j] - m);
            lse[tid] = m + logf(s);
        }
        __syncthreads();
        if (tid < RROLE * RROLE) la[tid] -= lse[tid / RROLE];
        __syncthreads();
        if (tid < RROLE) {
            float m = -1e30f;
            for (int i = 0; i < RROLE; i++) m = fmaxf(m, la[i * RROLE + tid]);
            float s = 0.0f;
            for (int i = 0; i < RROLE; i++) s += expf(la[i * RROLE + tid] - m);
            lse[tid] = m + logf(s);
        }
        __syncthreads();
        if (tid < RROLE * RROLE) la[tid] -= lse[tid % RROLE];
        __syncthreads();
    }

    if (tid < RROLE * RROLE) {
        float mv = expf(la[tid]);
        map_s[tid] = mv;
        out_mapping[(size_t)b * RROLE * RROLE + tid] = mv;
    }
    __syncthreads();

    // mapped_src = mapping @ tgt_enc ; combined = [mapped, tgt] ; diff accumulation
    float local = 0.0f;
    for (int e = tid; e < RROLE * HDIM; e += 256) {
        int i = e >> 8;        // HDIM = 256
        int h = e & 255;
        float v = 0.0f;
#pragma unroll
        for (int j = 0; j < RROLE; j++) v += map_s[i * RROLE + j] * t_s[j * HDIM + h];
        out_mapped[base + e] = v;
        float* cb = combined + ((size_t)b * RROLE + i) * (2 * HDIM);
        cb[h] = v;
        cb[HDIM + h] = t_s[i * HDIM + h];
        local += fabsf(v - s_s[e]);
    }
    red[tid] = local;
    __syncthreads();
    for (int s = 128; s > 0; s >>= 1) {
        if (tid < s) red[tid] += red[tid + s];
        __syncthreads();
    }
    if (tid == 0) {
        float conf_in = red[0] * (1.0f / (RROLE * HDIM));
        float z = conf_in * Wc1[0] + bc1[0];
        out_conf[b] = 1.0f / (1.0f + expf(-z));
    }
}

// ------------------- launch -------------------
extern "C" void kernel_launch(void* const* d_in, const int* in_sizes, int n_in,
                              void* d_out, int out_size)
{
    (void)in_sizes; (void)n_in; (void)out_size;
    const float* src  = (const float*)d_in[0];
    const float* tgt  = (const float*)d_in[1];
    const float* W1   = (const float*)d_in[2];
    const float* b1   = (const float*)d_in[3];
    const float* g1   = (const float*)d_in[4];
    const float* Wa   = (const float*)d_in[5];
    const float* Wb   = (const float*)d_in[6];
    const float* Wc   = (const float*)d_in[7];
    const float* W2   = (const float*)d_in[8];
    const float* b2   = (const float*)d_in[9];
    const float* Wbil = (const float*)d_in[10];
    const float* bbil = (const float*)d_in[11];
    const float* Wa1  = (const float*)d_in[12];
    const float* ba1  = (const float*)d_in[13];
    const float* Wa2  = (const float*)d_in[14];
    const float* ba2  = (const float*)d_in[15];
    const float* g2   = (const float*)d_in[16];
    const float* Wc1  = (const float*)d_in[17];
    const float* bc1  = (const float*)d_in[18];
    float* out = (float*)d_out;

    float *Wf, *x1, *ab, *bbf, *encS, *encT, *ub, *comb;
    cudaGetSymbolAddress((void**)&Wf,   g_Wf);
    cudaGetSymbolAddress((void**)&x1,   g_x1);
    cudaGetSymbolAddress((void**)&ab,   g_ab);
    cudaGetSymbolAddress((void**)&bbf,  g_bb);
    cudaGetSymbolAddress((void**)&encS, g_enc_src);
    cudaGetSymbolAddress((void**)&encT, g_enc_tgt);
    cudaGetSymbolAddress((void**)&ub,   g_u);
    cudaGetSymbolAddress((void**)&comb, g_comb);

    const int M = MROWS;          // 49152, /64 = 768
    dim3 gN256(256 / 64, M / 64);
    dim3 gN512(512 / 64, M / 64);
    dim3 gN1024(1024 / 64, M / 64);

    // Wf = W2 @ Wc
    fusew_kernel<<<512, 256>>>(W2, Wc, Wf);

    for (int t = 0; t < 2; t++) {
        const float* X = t ? tgt : src;
        float* enc = t ? encT : encS;
        // layer1 + rmsnorm
        gemm64_kernel<false, 0><<<gN256, 256>>>(X, W1, b1, x1, M, HDIM, DDIM);
        rmsnorm_kernel<HDIM><<<M / 8, 256>>>(x1, g1, M);
        // SwiGLU
        gemm64_kernel<false, 0><<<gN512, 256>>>(x1, Wa, nullptr, ab,  M, 2 * HDIM, HDIM);
        gemm64_kernel<false, 0><<<gN512, 256>>>(x1, Wb, nullptr, bbf, M, 2 * HDIM, HDIM);
        {
            int n4 = M * 2 * HDIM / 4;
            swiglu_kernel<<<(n4 + 255) / 256, 256>>>((float4*)ab, (const float4*)bbf, n4);
        }
        // enc = h @ (W2@Wc)^T + b2
        gemm64_kernel<false, 0><<<gN256, 256>>>(ab, Wf, b2, enc, M, HDIM, 2 * HDIM);
    }

    // u = enc_src @ Wbil  (B stored [K,N])
    gemm64_kernel<true, 0><<<gN256, 256>>>(encS, Wbil, nullptr, ub, M, HDIM, HDIM);

    // per-batch: scores -> sinkhorn -> mapping/mapped_src/confidence/combined
    batch_kernel<<<BATCH, 256>>>(ub, encT, encS, bbil, Wc1, bc1,
                                 out + OUT_MAPPING_OFF, out + OUT_MAPPED_OFF,
                                 out + OUT_CONF_OFF, comb);

    // answer_proj: gelu(combined @ Wa1^T + ba1) @ Wa2^T + ba2, then rmsnorm(g2)
    gemm64_kernel<false, 1><<<gN512, 256>>>(comb, Wa1, ba1, ab, M, 2 * HDIM, 2 * HDIM);
    gemm64_kernel<false, 0><<<gN1024, 256>>>(ab, Wa2, ba2, out + OUT_ANSWER_OFF, M, DDIM, 2 * HDIM);
    rmsnorm_kernel<DDIM><<<M / 8, 256>>>(out + OUT_ANSWER_OFF, g2, M);
}

// round 2
// speedup vs baseline: 1.0001x; 1.0001x over previous
#include <cuda_runtime.h>
#include <cstdint>
#include <math.h>

// Problem constants
#define BATCH 8192
#define RROLE 6
#define DDIM 1024
#define HDIM 256
#define MROWS (BATCH * RROLE)          // 49152
#define TEMP_INV 2.0f                   // 1/TEMP, TEMP=0.5
#define SINKHORN_ITERS 5

// Output layout (flattened tuple: answer, mapping, mapped_src, confidence)
#define OUT_ANSWER_OFF  0
#define OUT_MAPPING_OFF ((size_t)MROWS * DDIM)                         // 50331648
#define OUT_MAPPED_OFF  (OUT_MAPPING_OFF + (size_t)BATCH * RROLE * RROLE)
#define OUT_CONF_OFF    (OUT_MAPPED_OFF + (size_t)MROWS * HDIM)

// ------------------- device scratch (no allocations allowed) -------------------
__device__ float g_Wf[HDIM * 2 * HDIM];            // 256x512 fused W2@Wc
__device__ float g_x1[(size_t)MROWS * HDIM];       // post layer1 + rmsnorm
__device__ float g_ab[(size_t)MROWS * 2 * HDIM];   // gate proj / swiglu hidden
__device__ float g_bb[(size_t)MROWS * 2 * HDIM];   // value proj
__device__ float g_enc_src[(size_t)MROWS * HDIM];
__device__ float g_enc_tgt[(size_t)MROWS * HDIM];
__device__ float g_u[(size_t)MROWS * HDIM];        // enc_src @ Wbil
__device__ float g_comb[(size_t)MROWS * 2 * HDIM]; // [mapped_src, tgt_enc]

// ------------------- activations -------------------
__device__ __forceinline__ float gelu_tanh(float x) {
    float x3 = x * x * x;
    return 0.5f * x * (1.0f + tanhf(0.7978845608028654f * (x + 0.044715f * x3)));
}

// ------------------- generic tiled GEMM: C = act(A @ op(B) + bias) -------------------
// A: [M,K] row-major. If !TRANSB: B is [N,K] row-major (PyTorch/JAX Linear weight,
// computes A@B^T). If TRANSB: B is [K,N] row-major (computes A@B).
// BM=BN=64, BK=16, 256 threads, 4x4 microtile. Requires M%64==0, N%64==0, K%16==0.
template <bool TRANSB, int ACT>
__global__ __launch_bounds__(256) void gemm64_kernel(
    const float* __restrict__ A, const float* __restrict__ B,
    const float* __restrict__ bias, float* __restrict__ C,
    int M, int N, int K)
{
    __shared__ float As[16][64];
    __shared__ float Bs[16][64];

    const int bm = blockIdx.y * 64;
    const int bn = blockIdx.x * 64;
    const int tid = threadIdx.x;
    const int tx = tid & 15;       // 0..15 -> n
    const int ty = tid >> 4;       // 0..15 -> m

    // load indices
    const int arow = tid >> 2;            // 0..63
    const int akg  = (tid & 3) * 4;       // 0,4,8,12
    const int brow = tid >> 4;            // 0..15 (TRANSB)
    const int bng  = (tid & 15) * 4;      // 0..60 (TRANSB)

    float acc[4][4];
#pragma unroll
    for (int i = 0; i < 4; i++)
#pragma unroll
        for (int j = 0; j < 4; j++) acc[i][j] = 0.0f;

    for (int k0 = 0; k0 < K; k0 += 16) {
        // A tile -> As[k][m]
        float4 av = *(const float4*)(A + (size_t)(bm + arow) * K + k0 + akg);
        As[akg + 0][arow] = av.x;
        As[akg + 1][arow] = av.y;
        As[akg + 2][arow] = av.z;
        As[akg + 3][arow] = av.w;

        if (!TRANSB) {
            float4 bv = *(const float4*)(B + (size_t)(bn + arow) * K + k0 + akg);
            Bs[akg + 0][arow] = bv.x;
            Bs[akg + 1][arow] = bv.y;
            Bs[akg + 2][arow] = bv.z;
            Bs[akg + 3][arow] = bv.w;
        } else {
            float4 bv = *(const float4*)(B + (size_t)(k0 + brow) * N + bn + bng);
            *(float4*)&Bs[brow][bng] = bv;
        }
        __syncthreads();

#pragma unroll
        for (int k = 0; k < 16; k++) {
            float4 a4 = *(const float4*)&As[k][ty * 4];
            float4 b4 = *(const float4*)&Bs[k][tx * 4];
            acc[0][0] += a4.x * b4.x; acc[0][1] += a4.x * b4.y;
            acc[0][2] += a4.x * b4.z; acc[0][3] += a4.x * b4.w;
            acc[1][0] += a4.y * b4.x; acc[1][1] += a4.y * b4.y;
            acc[1][2] += a4.y * b4.z; acc[1][3] += a4.y * b4.w;
            acc[2][0] += a4.z * b4.x; acc[2][1] += a4.z * b4.y;
            acc[2][2] += a4.z * b4.z; acc[2][3] += a4.z * b4.w;
            acc[3][0] += a4.w * b4.x; acc[3][1] += a4.w * b4.y;
            acc[3][2] += a4.w * b4.z; acc[3][3] += a4.w * b4.w;
        }
        __syncthreads();
    }

    float4 bv = make_float4(0.f, 0.f, 0.f, 0.f);
    if (bias) bv = *(const float4*)(bias + bn + tx * 4);

#pragma unroll
    for (int i = 0; i < 4; i++) {
        float4 o;
        o.x = acc[i][0] + bv.x;
        o.y = acc[i][1] + bv.y;
        o.z = acc[i][2] + bv.z;
        o.w = acc[i][3] + bv.w;
        if (ACT == 1) {
            o.x = gelu_tanh(o.x); o.y = gelu_tanh(o.y);
            o.z = gelu_tanh(o.z); o.w = gelu_tanh(o.w);
        }
        *(float4*)(C + (size_t)(bm + ty * 4 + i) * N + bn + tx * 4) = o;
    }
}

// ------------------- rmsnorm (in-place): x = x * rsqrt(mean(x^2)+1e-6) * g -------------------
template <int NC>
__global__ void rmsnorm_kernel(float* __restrict__ x, const float* __restrict__ g, int rows)
{
    int row = blockIdx.x * 8 + (threadIdx.x >> 5);
    int lane = threadIdx.x & 31;
    if (row >= rows) return;
    float* p = x + (size_t)row * NC;
    constexpr int V = NC / 32;
    float v[V];
    float ss = 0.0f;
#pragma unroll
    for (int i = 0; i < V; i++) { v[i] = p[lane + 32 * i]; ss += v[i] * v[i]; }
#pragma unroll
    for (int o = 16; o > 0; o >>= 1) ss += __shfl_xor_sync(0xffffffffu, ss, o);
    float sc = rsqrtf(ss * (1.0f / NC) + 1e-6f);
#pragma unroll
    for (int i = 0; i < V; i++) p[lane + 32 * i] = v[i] * sc * g[lane + 32 * i];
}

// ------------------- swiglu combine: a = silu(a) * b (elementwise, float4) -------------------
__global__ void swiglu_kernel(float4* __restrict__ a, const float4* __restrict__ b, int n4)
{
    int i = blockIdx.x * blockDim.x + threadIdx.x;
    if (i >= n4) return;
    float4 x = a[i];
    float4 y = b[i];
    x.x = x.x / (1.0f + expf(-x.x)) * y.x;
    x.y = x.y / (1.0f + expf(-x.y)) * y.y;
    x.z = x.z / (1.0f + expf(-x.z)) * y.z;
    x.w = x.w / (1.0f + expf(-x.w)) * y.w;
    a[i] = x;
}

// ------------------- fused weight: Wf[256,512] = W2[256,256] @ Wc[256,512] -------------------
__global__ void fusew_kernel(const float* __restrict__ W2, const float* __restrict__ Wc,
                             float* __restrict__ Wf)
{
    int idx = blockIdx.x * blockDim.x + threadIdx.x;   // 131072 threads
    int i = idx >> 9;
    int j = idx & 511;
    float s = 0.0f;
    for (int k = 0; k < 256; k++) s += W2[i * 256 + k] * Wc[k * 512 + j];
    Wf[idx] = s;
}

// ------------------- per-batch: scores, sinkhorn, mapping, mapped_src, confidence, combined ---
__global__ __launch_bounds__(256) void batch_kernel(
    const float* __restrict__ u,        // [B*R, H] = enc_src @ Wbil
    const float* __restrict__ tgt,      // [B*R, H]
    const float* __restrict__ src,      // [B*R, H]
    const float* __restrict__ bbil,
    const float* __restrict__ Wc1, const float* __restrict__ bc1,
    float* __restrict__ out_mapping,    // [B, R, R]
    float* __restrict__ out_mapped,     // [B, R, H]
    float* __restrict__ out_conf,       // [B]
    float* __restrict__ combined)       // [B*R, 2H]
{
    const int b = blockIdx.x;
    const int tid = threadIdx.x;
    __shared__ float u_s[RROLE * HDIM];
    __shared__ float t_s[RROLE * HDIM];
    __shared__ float s_s[RROLE * HDIM];
    __shared__ float la[RROLE * RROLE];
    __shared__ float map_s[RROLE * RROLE];
    __shared__ float lse[RROLE];
    __shared__ float red[256];

    const size_t base = (size_t)b * RROLE * HDIM;
    for (int e = tid; e < RROLE * HDIM; e += 256) {
        u_s[e] = u[base + e];
        t_s[e] = tgt[base + e];
        s_s[e] = src[base + e];
    }
    __syncthreads();

    // log_alpha[i][j] = (u[i] . tgt[j] + bbil) / TEMP
    const float bb = bbil[0];
    const int warp = tid >> 5, lane = tid & 31;
    for (int p = warp; p < RROLE * RROLE; p += 8) {
        int i = p / RROLE, j = p % RROLE;
        float d = 0.0f;
        for (int h = lane; h < HDIM; h += 32) d += u_s[i * HDIM + h] * t_s[j * HDIM + h];
#pragma unroll
        for (int o = 16; o > 0; o >>= 1) d += __shfl_xor_sync(0xffffffffu, d, o);
        if (lane == 0) la[p] = (d + bb) * TEMP_INV;
    }
    __syncthreads();

    // Sinkhorn: row-normalize (over j), then col-normalize (over i), x5
    for (int it = 0; it < SINKHORN_ITERS; it++) {
        if (tid < RROLE) {
            float m = -1e30f;
            for (int j = 0; j < RROLE; j++) m = fmaxf(m, la[tid * RROLE + j]);
            float s = 0.0f;
            for (int j = 0; j < RROLE; j++) s += expf(la[tid * RROLE + j] - m);
            lse[tid] = m + logf(s);
        }
        __syncthreads();
        if (tid < RROLE * RROLE) la[tid] -= lse[tid / RROLE];
        __syncthreads();
        if (tid < RROLE) {
            float m = -1e30f;
            for (int i = 0; i < RROLE; i++) m = fmaxf(m, la[i * RROLE + tid]);
            float s = 0.0f;
            for (int i = 0; i < RROLE; i++) s += expf(la[i * RROLE + tid] - m);
            lse[tid] = m + logf(s);
        }
        __syncthreads();
        if (tid < RROLE * RROLE) la[tid] -= lse[tid % RROLE];
        __syncthreads();
    }

    if (tid < RROLE * RROLE) {
        float mv = expf(la[tid]);
        map_s[tid] = mv;
        out_mapping[(size_t)b * RROLE * RROLE + tid] = mv;
    }
    __syncthreads();

    // mapped_src = mapping @ tgt_enc ; combined = [mapped, tgt] ; diff accumulation
    float local = 0.0f;
    for (int e = tid; e < RROLE * HDIM; e += 256) {
        int i = e >> 8;        // HDIM = 256
        int h = e & 255;
        float v = 0.0f;
#pragma unroll
        for (int j = 0; j < RROLE; j++) v += map_s[i * RROLE + j] * t_s[j * HDIM + h];
        out_mapped[base + e] = v;
        float* cb = combined + ((size_t)b * RROLE + i) * (2 * HDIM);
        cb[h] = v;
        cb[HDIM + h] = t_s[i * HDIM + h];
        local += fabsf(v - s_s[e]);
    }
    red[tid] = local;
    __syncthreads();
    for (int s = 128; s > 0; s >>= 1) {
        if (tid < s) red[tid] += red[tid + s];
        __syncthreads();
    }
    if (tid == 0) {
        float conf_in = red[0] * (1.0f / (RROLE * HDIM));
        float z = conf_in * Wc1[0] + bc1[0];
        out_conf[b] = 1.0f / (1.0f + expf(-z));
    }
}

// ------------------- launch -------------------
extern "C" void kernel_launch(void* const* d_in, const int* in_sizes, int n_in,
                              void* d_out, int out_size)
{
    (void)in_sizes; (void)n_in; (void)out_size;
    const float* src  = (const float*)d_in[0];
    const float* tgt  = (const float*)d_in[1];
    const float* W1   = (const float*)d_in[2];
    const float* b1   = (const float*)d_in[3];
    const float* g1   = (const float*)d_in[4];
    const float* Wa   = (const float*)d_in[5];
    const float* Wb   = (const float*)d_in[6];
    const float* Wc   = (const float*)d_in[7];
    const float* W2   = (const float*)d_in[8];
    const float* b2   = (const float*)d_in[9];
    const float* Wbil = (const float*)d_in[10];
    const float* bbil = (const float*)d_in[11];
    const float* Wa1  = (const float*)d_in[12];
    const float* ba1  = (const float*)d_in[13];
    const float* Wa2  = (const float*)d_in[14];
    const float* ba2  = (const float*)d_in[15];
    const float* g2   = (const float*)d_in[16];
    const float* Wc1  = (const float*)d_in[17];
    const float* bc1  = (const float*)d_in[18];
    float* out = (float*)d_out;

    float *Wf, *x1, *ab, *bbf, *encS, *encT, *ub, *comb;
    cudaGetSymbolAddress((void**)&Wf,   g_Wf);
    cudaGetSymbolAddress((void**)&x1,   g_x1);
    cudaGetSymbolAddress((void**)&ab,   g_ab);
    cudaGetSymbolAddress((void**)&bbf,  g_bb);
    cudaGetSymbolAddress((void**)&encS, g_enc_src);
    cudaGetSymbolAddress((void**)&encT, g_enc_tgt);
    cudaGetSymbolAddress((void**)&ub,   g_u);
    cudaGetSymbolAddress((void**)&comb, g_comb);

    const int M = MROWS;          // 49152, /64 = 768
    dim3 gN256(256 / 64, M / 64);
    dim3 gN512(512 / 64, M / 64);
    dim3 gN1024(1024 / 64, M / 64);

    // Wf = W2 @ Wc
    fusew_kernel<<<512, 256>>>(W2, Wc, Wf);

    for (int t = 0; t < 2; t++) {
        const float* X = t ? tgt : src;
        float* enc = t ? encT : encS;
        // layer1 + rmsnorm
        gemm64_kernel<false, 0><<<gN256, 256>>>(X, W1, b1, x1, M, HDIM, DDIM);
        rmsnorm_kernel<HDIM><<<M / 8, 256>>>(x1, g1, M);
        // SwiGLU
        gemm64_kernel<false, 0><<<gN512, 256>>>(x1, Wa, nullptr, ab,  M, 2 * HDIM, HDIM);
        gemm64_kernel<false, 0><<<gN512, 256>>>(x1, Wb, nullptr, bbf, M, 2 * HDIM, HDIM);
        {
            int n4 = M * 2 * HDIM / 4;
            swiglu_kernel<<<(n4 + 255) / 256, 256>>>((float4*)ab, (const float4*)bbf, n4);
        }
        // enc = h @ (W2@Wc)^T + b2
        gemm64_kernel<false, 0><<<gN256, 256>>>(ab, Wf, b2, enc, M, HDIM, 2 * HDIM);
    }

    // u = enc_src @ Wbil  (B stored [K,N])
    gemm64_kernel<true, 0><<<gN256, 256>>>(encS, Wbil, nullptr, ub, M, HDIM, HDIM);

    // per-batch: scores -> sinkhorn -> mapping/mapped_src/confidence/combined
    batch_kernel<<<BATCH, 256>>>(ub, encT, encS, bbil, Wc1, bc1,
                                 out + OUT_MAPPING_OFF, out + OUT_MAPPED_OFF,
                                 out + OUT_CONF_OFF, comb);

    // answer_proj: gelu(combined @ Wa1^T + ba1) @ Wa2^T + ba2, then rmsnorm(g2)
    gemm64_kernel<false, 1><<<gN512, 256>>>(comb, Wa1, ba1, ab, M, 2 * HDIM, 2 * HDIM);
    gemm64_kernel<false, 0><<<gN1024, 256>>>(ab, Wa2, ba2, out + OUT_ANSWER_OFF, M, DDIM, 2 * HDIM);
    rmsnorm_kernel<DDIM><<<M / 8, 256>>>(out + OUT_ANSWER_OFF, g2, M);
}

// round 4
// speedup vs baseline: 2.3577x; 2.3573x over previous
#include <cuda_runtime.h>
#include <cuda_fp16.h>
#include <cstdint>
#include <math.h>

#define BATCH 8192
#define RROLE 6
#define DDIM 1024
#define HDIM 256
#define MROWS (BATCH * RROLE)
#define TEMP_INV 2.0f
#define SINKHORN_ITERS 5

#define OUT_ANSWER_OFF  0
#define OUT_MAPPING_OFF ((size_t)MROWS * DDIM)
#define OUT_MAPPED_OFF  (OUT_MAPPING_OFF + (size_t)BATCH * RROLE * RROLE)
#define OUT_CONF_OFF    (OUT_MAPPED_OFF + (size_t)MROWS * HDIM)

#define WSCALE 1024.0f
#define ISCALE (1.0f / 1024.0f)

// ---------------- device scratch ----------------
__device__ float g_Wf[HDIM * 2 * HDIM];
__device__ float g_x1[(size_t)MROWS * HDIM];
__device__ float g_big[(size_t)MROWS * 1024];
__device__ float g_h[(size_t)MROWS * 512];
__device__ float g_enc_src[(size_t)MROWS * HDIM];
__device__ float g_enc_tgt[(size_t)MROWS * HDIM];
__device__ float g_u[(size_t)MROWS * HDIM];
__device__ float g_comb[(size_t)MROWS * 2 * HDIM];

// fp16 weight planes (2 planes each, scaled by WSCALE)
__device__ __half g_W1P [2 * 256 * 1024];
__device__ __half g_WabP[2 * 1024 * 256];
__device__ __half g_WfP [2 * 256 * 512];
__device__ __half g_WbTP[2 * 256 * 256];
__device__ __half g_Wa1P[2 * 512 * 512];
__device__ __half g_Wa2P[2 * 1024 * 512];

// ---------------- helpers ----------------
__device__ __forceinline__ uint32_t smem_u32(const void* p) {
    uint32_t a;
    asm("{ .reg .u64 t; cvta.to.shared.u64 t, %1; cvt.u32.u64 %0, t; }" : "=r"(a) : "l"(p));
    return a;
}
__device__ __forceinline__ float gelu_tanh(float x) {
    float x3 = x * x * x;
    return 0.5f * x * (1.0f + tanhf(0.7978845608028654f * (x + 0.044715f * x3)));
}
__device__ __forceinline__ void ldsm4(uint32_t& r0, uint32_t& r1, uint32_t& r2, uint32_t& r3,
                                      uint32_t addr) {
    asm volatile("ldmatrix.sync.aligned.m8n8.x4.shared.b16 {%0,%1,%2,%3}, [%4];"
                 : "=r"(r0), "=r"(r1), "=r"(r2), "=r"(r3) : "r"(addr));
}
__device__ __forceinline__ void mma16816(float* c, const uint32_t* a, const uint32_t* b) {
    asm volatile("mma.sync.aligned.m16n8k16.row.col.f32.f16.f16.f32 "
                 "{%0,%1,%2,%3}, {%4,%5,%6,%7}, {%8,%9}, {%0,%1,%2,%3};"
                 : "+f"(c[0]), "+f"(c[1]), "+f"(c[2]), "+f"(c[3])
                 : "r"(a[0]), "r"(a[1]), "r"(a[2]), "r"(a[3]), "r"(b[0]), "r"(b[1]));
}
__device__ __forceinline__ uint32_t packh(float x, float y) {
    __half h0 = __float2half(x), h1 = __float2half(y);
    return (uint32_t)__half_as_ushort(h0) | ((uint32_t)__half_as_ushort(h1) << 16);
}
#define CP_ASYNC16(dst, src) \
    asm volatile("cp.async.cg.shared.global [%0], [%1], 16;" :: "r"(dst), "l"(src) : "memory")
#define CP_COMMIT() asm volatile("cp.async.commit_group;" ::: "memory")
#define CP_WAIT0()  asm volatile("cp.async.wait_group 0;" ::: "memory")

// ---------------- HMMA GEMM: C[M,N] = act((A_f32 @ Bplanes^T) * ISCALE + bias) ----------------
// A [M,K] fp32 row-major (split to 2 fp16 planes in-kernel).
// Bp: 2 planes of [N,K] fp16 row-major (pre-scaled by WSCALE), plane stride pStride.
// BM=128, BN=64, BK=32. 256 threads, 8 warps (4m x 2n), warp tile 32x32.
// Requires M%128==0, N%64==0, K%32==0.
// smem buffer (bytes): Ah 0..10240, Al 10240..20480, Bh 20480..25600, Bl 25600..30720
// double buffered: total 61440
#define GBUF 30720
#define SMEM_GEMM 61440

template <int ACT>
__global__ __launch_bounds__(256, 2) void gemm_mma(
    const float* __restrict__ A, const __half* __restrict__ Bp,
    const float* __restrict__ bias, float* __restrict__ C,
    int M, int N, int K, int pStride)
{
    extern __shared__ char smem[];
    const uint32_t sb = smem_u32(smem);
    const int tid = threadIdx.x, lane = tid & 31, wid = tid >> 5;
    const int bm = blockIdx.y * 128, bn = blockIdx.x * 64;
    const int wm = (wid >> 1) * 32, wn = (wid & 1) * 32;

    // A load mapping: 128 rows x 32 fp32 cols; thread: row=tid>>1, col=(tid&1)*16
    const int arow = tid >> 1, acol = (tid & 1) * 16;
    const float* aBase = A + (size_t)(bm + arow) * K + acol;
    const uint32_t aSts = sb + (uint32_t)(arow * 80 + acol * 2);
    // B cp.async mapping: 64 rows x 32 halves, 4 x 16B segs: row=tid>>2, seg=tid&3
    const int brow = tid >> 2, bseg = tid & 3;
    const __half* bBase = Bp + (size_t)(bn + brow) * K + bseg * 8;
    const uint32_t bSts = sb + 20480u + (uint32_t)(brow * 80 + bseg * 16);

    // ldmatrix addresses (byte offsets within a buffer)
    // A: row = wm + mt*16 + (lane&15), colh = ks*16 + (lane>>4)*8
    const uint32_t aLd0 = sb + (uint32_t)((wm + (lane & 15)) * 80 + (lane >> 4) * 16);
    // B: n = wn + nt2*16 + (lane&7) + ((lane>>4)&1)*8, colh = ks*16 + ((lane>>3)&1)*8
    const uint32_t bLd0 = sb + 20480u +
        (uint32_t)(((wn + (lane & 7) + ((lane >> 4) & 1) * 8) * 80) + ((lane >> 3) & 1) * 16);

    float acc[2][4][4];
#pragma unroll
    for (int mt = 0; mt < 2; mt++)
#pragma unroll
        for (int nt = 0; nt < 4; nt++)
#pragma unroll
            for (int i = 0; i < 4; i++) acc[mt][nt][i] = 0.0f;

    const int nkb = K >> 5;

    // ---- prologue: stage kb=0 into buffer 0 ----
    {
        float v[16];
#pragma unroll
        for (int j = 0; j < 4; j++)
            *(float4*)(v + j * 4) = *(const float4*)(aBase + j * 4);
        uint32_t hp[8], lp[8];
#pragma unroll
        for (int j = 0; j < 8; j++) {
            __half h0 = __float2half(v[2 * j]), h1 = __float2half(v[2 * j + 1]);
            float l0 = v[2 * j] - __half2float(h0), l1 = v[2 * j + 1] - __half2float(h1);
            hp[j] = (uint32_t)__half_as_ushort(h0) | ((uint32_t)__half_as_ushort(h1) << 16);
            lp[j] = packh(l0, l1);
        }
        *(uint4*)(smem + (aSts - sb))        = *(uint4*)hp;
        *(uint4*)(smem + (aSts - sb) + 16)   = *(uint4*)(hp + 4);
        *(uint4*)(smem + (aSts - sb) + 10240)      = *(uint4*)lp;
        *(uint4*)(smem + (aSts - sb) + 10240 + 16) = *(uint4*)(lp + 4);
#pragma unroll
        for (int pl = 0; pl < 2; pl++)
            CP_ASYNC16(bSts + pl * 5120u, bBase + (size_t)pl * pStride);
        CP_COMMIT();
        CP_WAIT0();
        __syncthreads();
    }

    for (int kb = 0; kb < nkb; kb++) {
        const uint32_t cur = (uint32_t)(kb & 1) * GBUF;
        const uint32_t nxt = (uint32_t)((kb + 1) & 1) * GBUF;
        const bool has = (kb + 1) < nkb;

        float v[16];
        if (has) {
            const float* ap = aBase + (kb + 1) * 32;
#pragma unroll
            for (int j = 0; j < 4; j++)
                *(float4*)(v + j * 4) = *(const float4*)(ap + j * 4);
            const __half* bp = bBase + (kb + 1) * 32;
#pragma unroll
            for (int pl = 0; pl < 2; pl++)
                CP_ASYNC16(bSts + nxt + pl * 5120u, bp + (size_t)pl * pStride);
        }
        CP_COMMIT();

        // ---- MMA over current buffer ----
#pragma unroll
        for (int ks = 0; ks < 2; ks++) {
            uint32_t af[2][2][4];     // [mt][plane][4]
#pragma unroll
            for (int mt = 0; mt < 2; mt++)
#pragma unroll
                for (int pl = 0; pl < 2; pl++)
                    ldsm4(af[mt][pl][0], af[mt][pl][1], af[mt][pl][2], af[mt][pl][3],
                          aLd0 + cur + pl * 10240u + mt * 16 * 80 + ks * 32);
            uint32_t bf[2][4][2];     // [plane][nt][2]
#pragma unroll
            for (int pl = 0; pl < 2; pl++)
#pragma unroll
                for (int nt2 = 0; nt2 < 2; nt2++) {
                    uint32_t r0, r1, r2, r3;
                    ldsm4(r0, r1, r2, r3,
                          bLd0 + cur + pl * 5120u + nt2 * 16 * 80 + ks * 32);
                    bf[pl][nt2 * 2][0] = r0; bf[pl][nt2 * 2][1] = r1;
                    bf[pl][nt2 * 2 + 1][0] = r2; bf[pl][nt2 * 2 + 1][1] = r3;
                }
            // 3 products: hh, h*l, l*h
#pragma unroll
            for (int prod = 0; prod < 3; prod++) {
                const int apl = (prod == 2) ? 1 : 0;
                const int bpl = (prod == 1) ? 1 : 0;
#pragma unroll
                for (int mt = 0; mt < 2; mt++)
#pragma unroll
                    for (int nt = 0; nt < 4; nt++)
                        mma16816(acc[mt][nt], af[mt][apl], bf[bpl][nt]);
            }
        }

        if (has) {
            uint32_t hp[8], lp[8];
#pragma unroll
            for (int j = 0; j < 8; j++) {
                __half h0 = __float2half(v[2 * j]), h1 = __float2half(v[2 * j + 1]);
                float l0 = v[2 * j] - __half2float(h0), l1 = v[2 * j + 1] - __half2float(h1);
                hp[j] = (uint32_t)__half_as_ushort(h0) | ((uint32_t)__half_as_ushort(h1) << 16);
                lp[j] = packh(l0, l1);
            }
            uint32_t off = (aSts - sb) + nxt;
            *(uint4*)(smem + off)              = *(uint4*)hp;
            *(uint4*)(smem + off + 16)         = *(uint4*)(hp + 4);
            *(uint4*)(smem + off + 10240)      = *(uint4*)lp;
            *(uint4*)(smem + off + 10240 + 16) = *(uint4*)(lp + 4);
        }
        CP_WAIT0();
        __syncthreads();
    }

    // ---- epilogue ----
#pragma unroll
    for (int mt = 0; mt < 2; mt++) {
        int row0 = bm + wm + mt * 16 + (lane >> 2);
#pragma unroll
        for (int nt = 0; nt < 4; nt++) {
            int col0 = bn + wn + nt * 8 + (lane & 3) * 2;
            float b0 = 0.f, b1 = 0.f;
            if (bias) { b0 = bias[col0]; b1 = bias[col0 + 1]; }
            float o0 = acc[mt][nt][0] * ISCALE + b0;
            float o1 = acc[mt][nt][1] * ISCALE + b1;
            float o2 = acc[mt][nt][2] * ISCALE + b0;
            float o3 = acc[mt][nt][3] * ISCALE + b1;
            if (ACT == 1) {
                o0 = gelu_tanh(o0); o1 = gelu_tanh(o1);
                o2 = gelu_tanh(o2); o3 = gelu_tanh(o3);
            }
            *(float2*)(C + (size_t)row0 * N + col0) = make_float2(o0, o1);
            *(float2*)(C + (size_t)(row0 + 8) * N + col0) = make_float2(o2, o3);
        }
    }
}

// ---------------- weight prep (scaled 2-plane fp16 split) ----------------
__global__ void split_kernel(const float* __restrict__ W, __half* __restrict__ out,
                             int n, int off, int pstride)
{
    int i = blockIdx.x * 256 + threadIdx.x;
    if (i >= n) return;
    float r = W[i] * WSCALE;
    __half h = __float2half(r);
    out[off + i] = h;
    r -= __half2float(h);
    out[(size_t)pstride + off + i] = __float2half(r);
}

__global__ void tsplit_kernel(const float* __restrict__ W, __half* __restrict__ out)
{   // out[p][n][k] = W[k][n] * WSCALE, 256x256
    int i = blockIdx.x * 256 + threadIdx.x;
    int nrow = i >> 8, k = i & 255;
    float r = W[k * 256 + nrow] * WSCALE;
    __half h = __float2half(r);
    out[i] = h;
    r -= __half2float(h);
    out[65536 + i] = __float2half(r);
}

__global__ void fusew_kernel(const float* __restrict__ W2, const float* __restrict__ Wc,
                             float* __restrict__ Wf)
{
    int idx = blockIdx.x * blockDim.x + threadIdx.x;
    int i = idx >> 9, j = idx & 511;
    float s = 0.0f;
    for (int k = 0; k < 256; k++) s += W2[i * 256 + k] * Wc[k * 512 + j];
    Wf[idx] = s;
}

// ---------------- elementwise ----------------
template <int NC>
__global__ void rmsnorm_kernel(float* __restrict__ x, const float* __restrict__ g, int rows)
{
    int row = blockIdx.x * 8 + (threadIdx.x >> 5);
    int lane = threadIdx.x & 31;
    if (row >= rows) return;
    float* p = x + (size_t)row * NC;
    constexpr int V = NC / 32;
    float v[V];
    float ss = 0.0f;
#pragma unroll
    for (int i = 0; i < V; i++) { v[i] = p[lane + 32 * i]; ss += v[i] * v[i]; }
#pragma unroll
    for (int o = 16; o > 0; o >>= 1) ss += __shfl_xor_sync(0xffffffffu, ss, o);
    float sc = rsqrtf(ss * (1.0f / NC) + 1e-6f);
#pragma unroll
    for (int i = 0; i < V; i++) p[lane + 32 * i] = v[i] * sc * g[lane + 32 * i];
}

// c: [M,1024] (gate cols 0..511, value 512..1023) -> h[M,512]
__global__ void swiglu_fused(const float4* __restrict__ c, float4* __restrict__ h, int mrows)
{
    int idx = blockIdx.x * 256 + threadIdx.x;
    int m = idx >> 7, j = idx & 127;
    if (m >= mrows) return;
    float4 g = c[(size_t)m * 256 + j];
    float4 v = c[(size_t)m * 256 + 128 + j];
    g.x = g.x / (1.0f + expf(-g.x)) * v.x;
    g.y = g.y / (1.0f + expf(-g.y)) * v.y;
    g.z = g.z / (1.0f + expf(-g.z)) * v.z;
    g.w = g.w / (1.0f + expf(-g.w)) * v.w;
    h[(size_t)m * 128 + j] = g;
}

// ---------------- per-batch sinkhorn etc ----------------
__global__ __launch_bounds__(256) void batch_kernel(
    const float* __restrict__ u, const float* __restrict__ tgt,
    const float* __restrict__ src, const float* __restrict__ bbil,
    const float* __restrict__ Wc1, const float* __restrict__ bc1,
    float* __restrict__ out_mapping, float* __restrict__ out_mapped,
    float* __restrict__ out_conf, float* __restrict__ combined)
{
    const int b = blockIdx.x;
    const int tid = threadIdx.x;
    __shared__ float u_s[RROLE * HDIM];
    __shared__ float t_s[RROLE * HDIM];
    __shared__ float s_s[RROLE * HDIM];
    __shared__ float la[RROLE * RROLE];
    __shared__ float map_s[RROLE * RROLE];
    __shared__ float lse[RROLE];
    __shared__ float red[256];

    const size_t base = (size_t)b * RROLE * HDIM;
    for (int e = tid; e < RROLE * HDIM; e += 256) {
        u_s[e] = u[base + e];
        t_s[e] = tgt[base + e];
        s_s[e] = src[base + e];
    }
    __syncthreads();

    const float bb = bbil[0];
    const int warp = tid >> 5, lane = tid & 31;
    for (int p = warp; p < RROLE * RROLE; p += 8) {
        int i = p / RROLE, j = p % RROLE;
        float d = 0.0f;
        for (int h = lane; h < HDIM; h += 32) d += u_s[i * HDIM + h] * t_s[j * HDIM + h];
#pragma unroll
        for (int o = 16; o > 0; o >>= 1) d += __shfl_xor_sync(0xffffffffu, d, o);
        if (lane == 0) la[p] = (d + bb) * TEMP_INV;
    }
    __syncthreads();

    for (int it = 0; it < SINKHORN_ITERS; it++) {
        if (tid < RROLE) {
            float m = -1e30f;
            for (int j = 0; j < RROLE; j++) m = fmaxf(m, la[tid * RROLE + j]);
            float s = 0.0f;
            for (int j = 0; j < RROLE; j++) s += expf(la[tid * RROLE + j] - m);
            lse[tid] = m + logf(s);
        }
        __syncthreads();
        if (tid < RROLE * RROLE) la[tid] -= lse[tid / RROLE];
        __syncthreads();
        if (tid < RROLE) {
            float m = -1e30f;
            for (int i = 0; i < RROLE; i++) m = fmaxf(m, la[i * RROLE + tid]);
            float s = 0.0f;
            for (int i = 0; i < RROLE; i++) s += expf(la[i * RROLE + tid] - m);
            lse[tid] = m + logf(s);
        }
        __syncthreads();
        if (tid < RROLE * RROLE) la[tid] -= lse[tid % RROLE];
        __syncthreads();
    }

    if (tid < RROLE * RROLE) {
        float mv = expf(la[tid]);
        map_s[tid] = mv;
        out_mapping[(size_t)b * RROLE * RROLE + tid] = mv;
    }
    __syncthreads();

    float local = 0.0f;
    for (int e = tid; e < RROLE * HDIM; e += 256) {
        int i = e >> 8;
        int h = e & 255;
        float v = 0.0f;
#pragma unroll
        for (int j = 0; j < RROLE; j++) v += map_s[i * RROLE + j] * t_s[j * HDIM + h];
        out_mapped[base + e] = v;
        float* cb = combined + ((size_t)b * RROLE + i) * (2 * HDIM);
        cb[h] = v;
        cb[HDIM + h] = t_s[i * HDIM + h];
        local += fabsf(v - s_s[e]);
    }
    red[tid] = local;
    __syncthreads();
    for (int s = 128; s > 0; s >>= 1) {
        if (tid < s) red[tid] += red[tid + s];
        __syncthreads();
    }
    if (tid == 0) {
        float conf_in = red[0] * (1.0f / (RROLE * HDIM));
        float z = conf_in * Wc1[0] + bc1[0];
        out_conf[b] = 1.0f / (1.0f + expf(-z));
    }
}

// ---------------- launch ----------------
extern "C" void kernel_launch(void* const* d_in, const int* in_sizes, int n_in,
                              void* d_out, int out_size)
{
    (void)in_sizes; (void)n_in; (void)out_size;
    const float* src  = (const float*)d_in[0];
    const float* tgt  = (const float*)d_in[1];
    const float* W1   = (const float*)d_in[2];
    const float* b1   = (const float*)d_in[3];
    const float* g1   = (const float*)d_in[4];
    const float* Wa   = (const float*)d_in[5];
    const float* Wb   = (const float*)d_in[6];
    const float* Wc   = (const float*)d_in[7];
    const float* W2   = (const float*)d_in[8];
    const float* b2   = (const float*)d_in[9];
    const float* Wbil = (const float*)d_in[10];
    const float* bbil = (const float*)d_in[11];
    const float* Wa1  = (const float*)d_in[12];
    const float* ba1  = (const float*)d_in[13];
    const float* Wa2  = (const float*)d_in[14];
    const float* ba2  = (const float*)d_in[15];
    const float* g2   = (const float*)d_in[16];
    const float* Wc1  = (const float*)d_in[17];
    const float* bc1  = (const float*)d_in[18];
    float* out = (float*)d_out;

    float *Wf, *x1, *big, *hbuf, *encS, *encT, *ub, *comb;
    __half *W1P, *WabP, *WfP, *WbTP, *Wa1P, *Wa2P;
    cudaGetSymbolAddress((void**)&Wf,   g_Wf);
    cudaGetSymbolAddress((void**)&x1,   g_x1);
    cudaGetSymbolAddress((void**)&big,  g_big);
    cudaGetSymbolAddress((void**)&hbuf, g_h);
    cudaGetSymbolAddress((void**)&encS, g_enc_src);
    cudaGetSymbolAddress((void**)&encT, g_enc_tgt);
    cudaGetSymbolAddress((void**)&ub,   g_u);
    cudaGetSymbolAddress((void**)&comb, g_comb);
    cudaGetSymbolAddress((void**)&W1P,  g_W1P);
    cudaGetSymbolAddress((void**)&WabP, g_WabP);
    cudaGetSymbolAddress((void**)&WfP,  g_WfP);
    cudaGetSymbolAddress((void**)&WbTP, g_WbTP);
    cudaGetSymbolAddress((void**)&Wa1P, g_Wa1P);
    cudaGetSymbolAddress((void**)&Wa2P, g_Wa2P);

    cudaFuncSetAttribute(gemm_mma<0>, cudaFuncAttributeMaxDynamicSharedMemorySize, SMEM_GEMM);
    cudaFuncSetAttribute(gemm_mma<1>, cudaFuncAttributeMaxDynamicSharedMemorySize, SMEM_GEMM);

    const int M = MROWS;                  // 49152, /128 = 384

    // ---- weight prep ----
    fusew_kernel<<<512, 256>>>(W2, Wc, Wf);
    split_kernel<<<1024, 256>>>(W1, W1P, 262144, 0, 262144);
    split_kernel<<<512, 256>>>(Wa, WabP, 131072, 0, 262144);
    split_kernel<<<512, 256>>>(Wb, WabP, 131072, 131072, 262144);
    split_kernel<<<512, 256>>>(Wf, WfP, 131072, 0, 131072);
    tsplit_kernel<<<256, 256>>>(Wbil, WbTP);
    split_kernel<<<1024, 256>>>(Wa1, Wa1P, 262144, 0, 262144);
    split_kernel<<<2048, 256>>>(Wa2, Wa2P, 524288, 0, 524288);

    // ---- encoder (both sides) ----
    for (int t = 0; t < 2; t++) {
        const float* X = t ? tgt : src;
        float* enc = t ? encT : encS;
        gemm_mma<0><<<dim3(4, 384), 256, SMEM_GEMM>>>(X, W1P, b1, x1, M, 256, 1024, 262144);
        rmsnorm_kernel<HDIM><<<M / 8, 256>>>(x1, g1, M);
        gemm_mma<0><<<dim3(16, 384), 256, SMEM_GEMM>>>(x1, WabP, nullptr, big, M, 1024, 256, 262144);
        swiglu_fused<<<M * 128 / 256, 256>>>((const float4*)big, (float4*)hbuf, M);
        gemm_mma<0><<<dim3(4, 384), 256, SMEM_GEMM>>>(hbuf, WfP, b2, enc, M, 256, 512, 131072);
    }

    // ---- bilinear u = encS @ Wbil ----
    gemm_mma<0><<<dim3(4, 384), 256, SMEM_GEMM>>>(encS, WbTP, nullptr, ub, M, 256, 256, 65536);

    // ---- sinkhorn / mapping / confidence / combined ----
    batch_kernel<<<BATCH, 256>>>(ub, encT, encS, bbil, Wc1, bc1,
                                 out + OUT_MAPPING_OFF, out + OUT_MAPPED_OFF,
                                 out + OUT_CONF_OFF, comb);

    // ---- answer projection ----
    gemm_mma<1><<<dim3(8, 384), 256, SMEM_GEMM>>>(comb, Wa1P, ba1, big, M, 512, 512, 262144);
    gemm_mma<0><<<dim3(16, 384), 256, SMEM_GEMM>>>(big, Wa2P, ba2, out + OUT_ANSWER_OFF, M, 1024, 512, 524288);
    rmsnorm_kernel<DDIM><<<M / 8, 256>>>(out + OUT_ANSWER_OFF, g2, M);
}

// round 5
// speedup vs baseline: 2.7691x; 1.1745x over previous
#include <cuda_runtime.h>
#include <cuda_fp16.h>
#include <cstdint>
#include <math.h>

#define BATCH 8192
#define RROLE 6
#define DDIM 1024
#define HDIM 256
#define MROWS (BATCH * RROLE)
#define TEMP_INV 2.0f
#define SINKHORN_ITERS 5

#define OUT_ANSWER_OFF  0
#define OUT_MAPPING_OFF ((size_t)MROWS * DDIM)
#define OUT_MAPPED_OFF  (OUT_MAPPING_OFF + (size_t)BATCH * RROLE * RROLE)
#define OUT_CONF_OFF    (OUT_MAPPED_OFF + (size_t)MROWS * HDIM)

#define WSCALE 1024.0f
#define ISCALE (1.0f / 1024.0f)

// plane strides (elements per plane)
#define PS_256 (MROWS * 256)
#define PS_512 (MROWS * 512)

// ---------------- device scratch ----------------
__device__ float g_Wf[HDIM * 2 * HDIM];
__device__ float g_x1[(size_t)MROWS * HDIM];
__device__ float g_enc_src[(size_t)MROWS * HDIM];
__device__ float g_enc_tgt[(size_t)MROWS * HDIM];
__device__ float g_u[(size_t)MROWS * HDIM];

// fp16 activation planes (2 planes each: hi @0, lo @plane-stride)
__device__ __half g_x1P  [2 * (size_t)MROWS * 256];
__device__ __half g_hP   [2 * (size_t)MROWS * 512];
__device__ __half g_encSP[2 * (size_t)MROWS * 256];
__device__ __half g_combP[2 * (size_t)MROWS * 512];
__device__ __half g_bigP [2 * (size_t)MROWS * 512];

// fp16 weight planes (2 planes each, scaled by WSCALE)
__device__ __half g_W1P [2 * 256 * 1024];
__device__ __half g_WabP[2 * 1024 * 256];   // interleaved gate/value rows
__device__ __half g_WfP [2 * 256 * 512];
__device__ __half g_WbTP[2 * 256 * 256];
__device__ __half g_Wa1P[2 * 512 * 512];
__device__ __half g_Wa2P[2 * 1024 * 512];

// ---------------- helpers ----------------
__device__ __forceinline__ uint32_t smem_u32(const void* p) {
    uint32_t a;
    asm("{ .reg .u64 t; cvta.to.shared.u64 t, %1; cvt.u32.u64 %0, t; }" : "=r"(a) : "l"(p));
    return a;
}
__device__ __forceinline__ float gelu_tanh(float x) {
    float x3 = x * x * x;
    return 0.5f * x * (1.0f + tanhf(0.7978845608028654f * (x + 0.044715f * x3)));
}
__device__ __forceinline__ void ldsm4(uint32_t& r0, uint32_t& r1, uint32_t& r2, uint32_t& r3,
                                      uint32_t addr) {
    asm volatile("ldmatrix.sync.aligned.m8n8.x4.shared.b16 {%0,%1,%2,%3}, [%4];"
                 : "=r"(r0), "=r"(r1), "=r"(r2), "=r"(r3) : "r"(addr));
}
__device__ __forceinline__ void mma16816(float* c, const uint32_t* a, const uint32_t* b) {
    asm volatile("mma.sync.aligned.m16n8k16.row.col.f32.f16.f16.f32 "
                 "{%0,%1,%2,%3}, {%4,%5,%6,%7}, {%8,%9}, {%0,%1,%2,%3};"
                 : "+f"(c[0]), "+f"(c[1]), "+f"(c[2]), "+f"(c[3])
                 : "r"(a[0]), "r"(a[1]), "r"(a[2]), "r"(a[3]), "r"(b[0]), "r"(b[1]));
}
__device__ __forceinline__ uint32_t packh(float x, float y) {
    __half h0 = __float2half(x), h1 = __float2half(y);
    return (uint32_t)__half_as_ushort(h0) | ((uint32_t)__half_as_ushort(h1) << 16);
}
#define CP_ASYNC16(dst, src) \
    asm volatile("cp.async.cg.shared.global [%0], [%1], 16;" :: "r"(dst), "l"(src) : "memory")
#define CP_COMMIT() asm volatile("cp.async.commit_group;" ::: "memory")
#define CP_WAIT0()  asm volatile("cp.async.wait_group 0;" ::: "memory")

// ---------------- HMMA GEMM ----------------
// C[M,Nout] = act((A @ Bplanes^T) * ISCALE + bias)
// MODE_A: 0 = A fp32 [M,K], split to fp16 planes in-kernel
//         1 = A pre-split fp16 planes (hi @0, lo @aPstride)
// ACT: 0 none, 1 gelu, 2 swiglu (B rows interleaved 32 gate + 32 value per 64)
// OUTMODE bit0: write fp32 Cf; bit1: write fp16 planes Cp (hi @0, lo @cPstride)
// BM=128, BN=64(weight rows), BK=32. 256 threads, 8 warps (4m x 2n), warp tile 32x32.
// smem/buffer: Ah 0..10240, Al 10240..20480, Bh 20480..25600, Bl 25600..30720
#define GBUF 30720
#define SMEM_GEMM 61440

template <int MODE_A, int ACT, int OUTMODE>
__global__ __launch_bounds__(256, 2) void gemm_mma(
    const void* __restrict__ Av, int aPstride,
    const __half* __restrict__ Bp, int bPstride,
    const float* __restrict__ bias,
    float* __restrict__ Cf,
    __half* __restrict__ Cp, size_t cPstride,
    int M, int N, int K, int Nout)
{
    extern __shared__ char smem[];
    const uint32_t sb = smem_u32(smem);
    const int tid = threadIdx.x, lane = tid & 31, wid = tid >> 5;
    const int bm = blockIdx.y * 128, bn = blockIdx.x * 64;
    const int wm = (wid >> 1) * 32, wn = (wid & 1) * 32;

    // ldmatrix addresses
    const uint32_t aLd0 = sb + (uint32_t)((wm + (lane & 15)) * 80 + (lane >> 4) * 16);
    const uint32_t bLd0 = sb + 20480u +
        (uint32_t)(((wn + (lane & 7) + ((lane >> 4) & 1) * 8) * 80) + ((lane >> 3) & 1) * 16);

    float acc[2][4][4];
#pragma unroll
    for (int mt = 0; mt < 2; mt++)
#pragma unroll
        for (int nt = 0; nt < 4; nt++)
#pragma unroll
            for (int i = 0; i < 4; i++) acc[mt][nt][i] = 0.0f;

    const int nkb = K >> 5;

    // -------- MODE_A == 0 state --------
    const int arow = tid >> 1, acol = (tid & 1) * 16;
    const float* aBaseF = (MODE_A == 0) ? ((const float*)Av + (size_t)(bm + arow) * K + acol) : nullptr;
    const uint32_t aStsOff = (uint32_t)(arow * 80 + acol * 2);
    const int brow0 = tid >> 2, bseg0 = tid & 3;
    const __half* bBase0 = Bp + (size_t)(bn + brow0) * K + bseg0 * 8;
    const uint32_t bSts0 = sb + 20480u + (uint32_t)(brow0 * 80 + bseg0 * 16);

    if (MODE_A == 1) {
        // prologue buffer 0
        const __half* Ap = (const __half*)Av;
#pragma unroll
        for (int t = 0; t < 4; t++) {
            int idx = t * 256 + tid;
            int pl = idx >> 9, row = (idx >> 2) & 127, s = idx & 3;
            const __half* srcp = Ap + (size_t)pl * aPstride + (size_t)(bm + row) * K + s * 8;
            CP_ASYNC16(sb + pl * 10240u + row * 80u + s * 16u, srcp);
        }
#pragma unroll
        for (int t = 0; t < 2; t++) {
            int idx = t * 256 + tid;
            int pl = idx >> 8, row = (idx >> 2) & 63, s = idx & 3;
            const __half* srcp = Bp + (size_t)pl * bPstride + (size_t)(bn + row) * K + s * 8;
            CP_ASYNC16(sb + 20480u + pl * 5120u + row * 80u + s * 16u, srcp);
        }
        CP_COMMIT();
        CP_WAIT0();
        __syncthreads();
    } else {
        float v[16];
#pragma unroll
        for (int j = 0; j < 4; j++)
            *(float4*)(v + j * 4) = *(const float4*)(aBaseF + j * 4);
        uint32_t hp[8], lp[8];
#pragma unroll
        for (int j = 0; j < 8; j++) {
            __half h0 = __float2half(v[2 * j]), h1 = __float2half(v[2 * j + 1]);
            hp[j] = (uint32_t)__half_as_ushort(h0) | ((uint32_t)__half_as_ushort(h1) << 16);
            lp[j] = packh(v[2 * j] - __half2float(h0), v[2 * j + 1] - __half2float(h1));
        }
        *(uint4*)(smem + aStsOff)              = *(uint4*)hp;
        *(uint4*)(smem + aStsOff + 16)         = *(uint4*)(hp + 4);
        *(uint4*)(smem + aStsOff + 10240)      = *(uint4*)lp;
        *(uint4*)(smem + aStsOff + 10240 + 16) = *(uint4*)(lp + 4);
#pragma unroll
        for (int pl = 0; pl < 2; pl++)
            CP_ASYNC16(bSts0 + pl * 5120u, bBase0 + (size_t)pl * bPstride);
        CP_COMMIT();
        CP_WAIT0();
        __syncthreads();
    }

    for (int kb = 0; kb < nkb; kb++) {
        const uint32_t cur = (uint32_t)(kb & 1) * GBUF;
        const uint32_t nxt = (uint32_t)((kb + 1) & 1) * GBUF;
        const bool has = (kb + 1) < nkb;

        float vstage[16];
        if (has) {
            if (MODE_A == 1) {
                const __half* Ap = (const __half*)Av;
#pragma unroll
                for (int t = 0; t < 4; t++) {
                    int idx = t * 256 + tid;
                    int pl = idx >> 9, row = (idx >> 2) & 127, s = idx & 3;
                    const __half* srcp = Ap + (size_t)pl * aPstride + (size_t)(bm + row) * K
                                         + (kb + 1) * 32 + s * 8;
                    CP_ASYNC16(sb + nxt + pl * 10240u + row * 80u + s * 16u, srcp);
                }
#pragma unroll
                for (int t = 0; t < 2; t++) {
                    int idx = t * 256 + tid;
                    int pl = idx >> 8, row = (idx >> 2) & 63, s = idx & 3;
                    const __half* srcp = Bp + (size_t)pl * bPstride + (size_t)(bn + row) * K
                                         + (kb + 1) * 32 + s * 8;
                    CP_ASYNC16(sb + nxt + 20480u + pl * 5120u + row * 80u + s * 16u, srcp);
                }
            } else {
                const float* ap = aBaseF + (kb + 1) * 32;
#pragma unroll
                for (int j = 0; j < 4; j++)
                    *(float4*)(vstage + j * 4) = *(const float4*)(ap + j * 4);
                const __half* bp = bBase0 + (kb + 1) * 32;
#pragma unroll
                for (int pl = 0; pl < 2; pl++)
                    CP_ASYNC16(bSts0 + nxt + pl * 5120u, bp + (size_t)pl * bPstride);
            }
        }
        CP_COMMIT();

        // ---- MMA over current buffer ----
#pragma unroll
        for (int ks = 0; ks < 2; ks++) {
            uint32_t af[2][2][4];
#pragma unroll
            for (int mt = 0; mt < 2; mt++)
#pragma unroll
                for (int pl = 0; pl < 2; pl++)
                    ldsm4(af[mt][pl][0], af[mt][pl][1], af[mt][pl][2], af[mt][pl][3],
                          aLd0 + cur + pl * 10240u + mt * 16 * 80 + ks * 32);
            uint32_t bf[2][4][2];
#pragma unroll
            for (int pl = 0; pl < 2; pl++)
#pragma unroll
                for (int nt2 = 0; nt2 < 2; nt2++) {
                    uint32_t r0, r1, r2, r3;
                    ldsm4(r0, r1, r2, r3,
                          bLd0 + cur + pl * 5120u + nt2 * 16 * 80 + ks * 32);
                    bf[pl][nt2 * 2][0] = r0; bf[pl][nt2 * 2][1] = r1;
                    bf[pl][nt2 * 2 + 1][0] = r2; bf[pl][nt2 * 2 + 1][1] = r3;
                }
#pragma unroll
            for (int prod = 0; prod < 3; prod++) {
                const int apl = (prod == 2) ? 1 : 0;
                const int bpl = (prod == 1) ? 1 : 0;
#pragma unroll
                for (int mt = 0; mt < 2; mt++)
#pragma unroll
                    for (int nt = 0; nt < 4; nt++)
                        mma16816(acc[mt][nt], af[mt][apl], bf[bpl][nt]);
            }
        }

        if (has && MODE_A == 0) {
            uint32_t hp[8], lp[8];
#pragma unroll
            for (int j = 0; j < 8; j++) {
                __half h0 = __float2half(vstage[2 * j]), h1 = __float2half(vstage[2 * j + 1]);
                hp[j] = (uint32_t)__half_as_ushort(h0) | ((uint32_t)__half_as_ushort(h1) << 16);
                lp[j] = packh(vstage[2 * j] - __half2float(h0), vstage[2 * j + 1] - __half2float(h1));
            }
            uint32_t off = aStsOff + nxt;
            *(uint4*)(smem + off)              = *(uint4*)hp;
            *(uint4*)(smem + off + 16)         = *(uint4*)(hp + 4);
            *(uint4*)(smem + off + 10240)      = *(uint4*)lp;
            *(uint4*)(smem + off + 10240 + 16) = *(uint4*)(lp + 4);
        }
        CP_WAIT0();
        __syncthreads();
    }

    // ---- epilogue ----
    if (ACT == 2) {
        // swiglu: value warps (wn=32) stash acc in smem; gate warps combine
        float* vs = (float*)smem;
        if (wn == 32) {
#pragma unroll
            for (int mt = 0; mt < 2; mt++)
#pragma unroll
                for (int nt = 0; nt < 4; nt++) {
                    int r0 = wm + mt * 16 + (lane >> 2);
                    int c = nt * 8 + (lane & 3) * 2;
                    vs[r0 * 34 + c]       = acc[mt][nt][0] * ISCALE;
                    vs[r0 * 34 + c + 1]   = acc[mt][nt][1] * ISCALE;
                    vs[(r0 + 8) * 34 + c]     = acc[mt][nt][2] * ISCALE;
                    vs[(r0 + 8) * 34 + c + 1] = acc[mt][nt][3] * ISCALE;
                }
        }
        __syncthreads();
        if (wn == 0) {
#pragma unroll
            for (int mt = 0; mt < 2; mt++) {
                int r0 = wm + mt * 16 + (lane >> 2);
#pragma unroll
                for (int nt = 0; nt < 4; nt++) {
                    int c = nt * 8 + (lane & 3) * 2;
                    float g0 = acc[mt][nt][0] * ISCALE, g1 = acc[mt][nt][1] * ISCALE;
                    float g2 = acc[mt][nt][2] * ISCALE, g3 = acc[mt][nt][3] * ISCALE;
                    float o0 = g0 / (1.0f + expf(-g0)) * vs[r0 * 34 + c];
                    float o1 = g1 / (1.0f + expf(-g1)) * vs[r0 * 34 + c + 1];
                    float o2 = g2 / (1.0f + expf(-g2)) * vs[(r0 + 8) * 34 + c];
                    float o3 = g3 / (1.0f + expf(-g3)) * vs[(r0 + 8) * 34 + c + 1];
                    size_t row = (size_t)(bm + r0);
                    int col = (bn >> 1) + c;
                    __half h0 = __float2half(o0), h1 = __float2half(o1);
                    __half h2 = __float2half(o2), h3 = __float2half(o3);
                    *(uint32_t*)(Cp + row * Nout + col) =
                        (uint32_t)__half_as_ushort(h0) | ((uint32_t)__half_as_ushort(h1) << 16);
                    *(uint32_t*)(Cp + cPstride + row * Nout + col) =
                        packh(o0 - __half2float(h0), o1 - __half2float(h1));
                    *(uint32_t*)(Cp + (row + 8) * Nout + col) =
                        (uint32_t)__half_as_ushort(h2) | ((uint32_t)__half_as_ushort(h3) << 16);
                    *(uint32_t*)(Cp + cPstride + (row + 8) * Nout + col) =
                        packh(o2 - __half2float(h2), o3 - __half2float(h3));
                }
            }
        }
        return;
    }

#pragma unroll
    for (int mt = 0; mt < 2; mt++) {
        int row0 = bm + wm + mt * 16 + (lane >> 2);
#pragma unroll
        for (int nt = 0; nt < 4; nt++) {
            int col0 = bn + wn + nt * 8 + (lane & 3) * 2;
            float b0 = 0.f, b1 = 0.f;
            if (bias) { b0 = bias[col0]; b1 = bias[col0 + 1]; }
            float o0 = acc[mt][nt][0] * ISCALE + b0;
            float o1 = acc[mt][nt][1] * ISCALE + b1;
            float o2 = acc[mt][nt][2] * ISCALE + b0;
            float o3 = acc[mt][nt][3] * ISCALE + b1;
            if (ACT == 1) {
                o0 = gelu_tanh(o0); o1 = gelu_tanh(o1);
                o2 = gelu_tanh(o2); o3 = gelu_tanh(o3);
            }
            if (OUTMODE & 1) {
                *(float2*)(Cf + (size_t)row0 * Nout + col0) = make_float2(o0, o1);
                *(float2*)(Cf + (size_t)(row0 + 8) * Nout + col0) = make_float2(o2, o3);
            }
            if (OUTMODE & 2) {
                __half h0 = __float2half(o0), h1 = __float2half(o1);
                __half h2 = __float2half(o2), h3 = __float2half(o3);
                *(uint32_t*)(Cp + (size_t)row0 * Nout + col0) =
                    (uint32_t)__half_as_ushort(h0) | ((uint32_t)__half_as_ushort(h1) << 16);
                *(uint32_t*)(Cp + cPstride + (size_t)row0 * Nout + col0) =
                    packh(o0 - __half2float(h0), o1 - __half2float(h1));
                *(uint32_t*)(Cp + (size_t)(row0 + 8) * Nout + col0) =
                    (uint32_t)__half_as_ushort(h2) | ((uint32_t)__half_as_ushort(h3) << 16);
                *(uint32_t*)(Cp + cPstride + (size_t)(row0 + 8) * Nout + col0) =
                    packh(o2 - __half2float(h2), o3 - __half2float(h3));
            }
        }
    }
}

// ---------------- weight prep ----------------
__global__ void split_kernel(const float* __restrict__ W, __half* __restrict__ out,
                             int n, int pstride)
{
    int i = blockIdx.x * 256 + threadIdx.x;
    if (i >= n) return;
    float r = W[i] * WSCALE;
    __half h = __float2half(r);
    out[i] = h;
    r -= __half2float(h);
    out[(size_t)pstride + i] = __float2half(r);
}

// WabP: interleave Wa/Wb rows in 32-row groups: block j rows 0-31 = Wa[j*32..],
// rows 32-63 = Wb[j*32..]. K=256.
__global__ void swab_split(const float* __restrict__ Wa, const float* __restrict__ Wb,
                           __half* __restrict__ out)
{
    int i = blockIdx.x * 256 + threadIdx.x;   // 262144
    int nrow = i >> 8, k = i & 255;
    int j = nrow >> 6, r = nrow & 63;
    float w = (r < 32) ? Wa[(j * 32 + r) * 256 + k] : Wb[(j * 32 + r - 32) * 256 + k];
    float rr = w * WSCALE;
    __half h = __float2half(rr);
    out[i] = h;
    rr -= __half2float(h);
    out[262144 + i] = __float2half(rr);
}

__global__ void tsplit_kernel(const float* __restrict__ W, __half* __restrict__ out)
{
    int i = blockIdx.x * 256 + threadIdx.x;
    int nrow = i >> 8, k = i & 255;
    float r = W[k * 256 + nrow] * WSCALE;
    __half h = __float2half(r);
    out[i] = h;
    r -= __half2float(h);
    out[65536 + i] = __float2half(r);
}

__global__ void fusew_kernel(const float* __restrict__ W2, const float* __restrict__ Wc,
                             float* __restrict__ Wf)
{
    int idx = blockIdx.x * blockDim.x + threadIdx.x;
    int i = idx >> 9, j = idx & 511;
    float s = 0.0f;
    for (int k = 0; k < 256; k++) s += W2[i * 256 + k] * Wc[k * 512 + j];
    Wf[idx] = s;
}

// ---------------- elementwise ----------------
template <int NC>
__global__ void rmsnorm_kernel(float* __restrict__ x, const float* __restrict__ g, int rows)
{
    int row = blockIdx.x * 8 + (threadIdx.x >> 5);
    int lane = threadIdx.x & 31;
    if (row >= rows) return;
    float* p = x + (size_t)row * NC;
    constexpr int V = NC / 32;
    float v[V];
    float ss = 0.0f;
#pragma unroll
    for (int i = 0; i < V; i++) { v[i] = p[lane + 32 * i]; ss += v[i] * v[i]; }
#pragma unroll
    for (int o = 16; o > 0; o >>= 1) ss += __shfl_xor_sync(0xffffffffu, ss, o);
    float sc = rsqrtf(ss * (1.0f / NC) + 1e-6f);
#pragma unroll
    for (int i = 0; i < V; i++) p[lane + 32 * i] = v[i] * sc * g[lane + 32 * i];
}

// rmsnorm reading fp32, writing fp16 planes
__global__ void rmsnorm_planes(const float* __restrict__ x, const float* __restrict__ g,
                               __half* __restrict__ out, int rows)
{
    int row = blockIdx.x * 8 + (threadIdx.x >> 5);
    int lane = threadIdx.x & 31;
    if (row >= rows) return;
    const float* p = x + (size_t)row * 256;
    float v[8];
    float ss = 0.0f;
#pragma unroll
    for (int i = 0; i < 8; i++) { v[i] = p[lane + 32 * i]; ss += v[i] * v[i]; }
#pragma unroll
    for (int o = 16; o > 0; o >>= 1) ss += __shfl_xor_sync(0xffffffffu, ss, o);
    float sc = rsqrtf(ss * (1.0f / 256.0f) + 1e-6f);
#pragma unroll
    for (int i = 0; i < 8; i++) {
        float o = v[i] * sc * g[lane + 32 * i];
        __half h = __float2half(o);
        out[(size_t)row * 256 + lane + 32 * i] = h;
        out[(size_t)PS_256 + (size_t)row * 256 + lane + 32 * i] = __float2half(o - __half2float(h));
    }
}

// ---------------- per-batch sinkhorn etc ----------------
__global__ __launch_bounds__(256) void batch_kernel(
    const float* __restrict__ u, const float* __restrict__ tgt,
    const float* __restrict__ src, const float* __restrict__ bbil,
    const float* __restrict__ Wc1, const float* __restrict__ bc1,
    float* __restrict__ out_mapping, float* __restrict__ out_mapped,
    float* __restrict__ out_conf, __half* __restrict__ combP)
{
    const int b = blockIdx.x;
    const int tid = threadIdx.x;
    __shared__ float u_s[RROLE * HDIM];
    __shared__ float t_s[RROLE * HDIM];
    __shared__ float s_s[RROLE * HDIM];
    __shared__ float la[RROLE * RROLE];
    __shared__ float map_s[RROLE * RROLE];
    __shared__ float lse[RROLE];
    __shared__ float red[256];

    const size_t base = (size_t)b * RROLE * HDIM;
    for (int e = tid; e < RROLE * HDIM; e += 256) {
        u_s[e] = u[base + e];
        t_s[e] = tgt[base + e];
        s_s[e] = src[base + e];
    }
    __syncthreads();

    const float bb = bbil[0];
    const int warp = tid >> 5, lane = tid & 31;
    for (int p = warp; p < RROLE * RROLE; p += 8) {
        int i = p / RROLE, j = p % RROLE;
        float d = 0.0f;
        for (int h = lane; h < HDIM; h += 32) d += u_s[i * HDIM + h] * t_s[j * HDIM + h];
#pragma unroll
        for (int o = 16; o > 0; o >>= 1) d += __shfl_xor_sync(0xffffffffu, d, o);
        if (lane == 0) la[p] = (d + bb) * TEMP_INV;
    }
    __syncthreads();

    for (int it = 0; it < SINKHORN_ITERS; it++) {
        if (tid < RROLE) {
            float m = -1e30f;
            for (int j = 0; j < RROLE; j++) m = fmaxf(m, la[tid * RROLE + j]);
            float s = 0.0f;
            for (int j = 0; j < RROLE; j++) s += expf(la[tid * RROLE + j] - m);
            lse[tid] = m + logf(s);
        }
        __syncthreads();
        if (tid < RROLE * RROLE) la[tid] -= lse[tid / RROLE];
        __syncthreads();
        if (tid < RROLE) {
            float m = -1e30f;
            for (int i = 0; i < RROLE; i++) m = fmaxf(m, la[i * RROLE + tid]);
            float s = 0.0f;
            for (int i = 0; i < RROLE; i++) s += expf(la[i * RROLE + tid] - m);
            lse[tid] = m + logf(s);
        }
        __syncthreads();
        if (tid < RROLE * RROLE) la[tid] -= lse[tid % RROLE];
        __syncthreads();
    }

    if (tid < RROLE * RROLE) {
        float mv = expf(la[tid]);
        map_s[tid] = mv;
        out_mapping[(size_t)b * RROLE * RROLE + tid] = mv;
    }
    __syncthreads();

    float local = 0.0f;
    for (int e = tid; e < RROLE * HDIM; e += 256) {
        int i = e >> 8;
        int h = e & 255;
        float v = 0.0f;
#pragma unroll
        for (int j = 0; j < RROLE; j++) v += map_s[i * RROLE + j] * t_s[j * HDIM + h];
        out_mapped[base + e] = v;
        size_t cbase = ((size_t)b * RROLE + i) * 512;
        __half vh = __float2half(v);
        combP[cbase + h] = vh;
        combP[(size_t)PS_512 + cbase + h] = __float2half(v - __half2float(vh));
        float t = t_s[i * HDIM + h];
        __half th = __float2half(t);
        combP[cbase + 256 + h] = th;
        combP[(size_t)PS_512 + cbase + 256 + h] = __float2half(t - __half2float(th));
        local += fabsf(v - s_s[e]);
    }
    red[tid] = local;
    __syncthreads();
    for (int s = 128; s > 0; s >>= 1) {
        if (tid < s) red[tid] += red[tid + s];
        __syncthreads();
    }
    if (tid == 0) {
        float conf_in = red[0] * (1.0f / (RROLE * HDIM));
        float z = conf_in * Wc1[0] + bc1[0];
        out_conf[b] = 1.0f / (1.0f + expf(-z));
    }
}

// ---------------- launch ----------------
extern "C" void kernel_launch(void* const* d_in, const int* in_sizes, int n_in,
                              void* d_out, int out_size)
{
    (void)in_sizes; (void)n_in; (void)out_size;
    const float* src  = (const float*)d_in[0];
    const float* tgt  = (const float*)d_in[1];
    const float* W1   = (const float*)d_in[2];
    const float* b1   = (const float*)d_in[3];
    const float* g1   = (const float*)d_in[4];
    const float* Wa   = (const float*)d_in[5];
    const float* Wb   = (const float*)d_in[6];
    const float* Wc   = (const float*)d_in[7];
    const float* W2   = (const float*)d_in[8];
    const float* b2   = (const float*)d_in[9];
    const float* Wbil = (const float*)d_in[10];
    const float* bbil = (const float*)d_in[11];
    const float* Wa1  = (const float*)d_in[12];
    const float* ba1  = (const float*)d_in[13];
    const float* Wa2  = (const float*)d_in[14];
    const float* ba2  = (const float*)d_in[15];
    const float* g2   = (const float*)d_in[16];
    const float* Wc1  = (const float*)d_in[17];
    const float* bc1  = (const float*)d_in[18];
    float* out = (float*)d_out;

    float *Wf, *x1, *encS, *encT, *ub;
    __half *x1P, *hP, *encSP, *combP, *bigP;
    __half *W1P, *WabP, *WfP, *WbTP, *Wa1P, *Wa2P;
    cudaGetSymbolAddress((void**)&Wf,    g_Wf);
    cudaGetSymbolAddress((void**)&x1,    g_x1);
    cudaGetSymbolAddress((void**)&encS,  g_enc_src);
    cudaGetSymbolAddress((void**)&encT,  g_enc_tgt);
    cudaGetSymbolAddress((void**)&ub,    g_u);
    cudaGetSymbolAddress((void**)&x1P,   g_x1P);
    cudaGetSymbolAddress((void**)&hP,    g_hP);
    cudaGetSymbolAddress((void**)&encSP, g_encSP);
    cudaGetSymbolAddress((void**)&combP, g_combP);
    cudaGetSymbolAddress((void**)&bigP,  g_bigP);
    cudaGetSymbolAddress((void**)&W1P,   g_W1P);
    cudaGetSymbolAddress((void**)&WabP,  g_WabP);
    cudaGetSymbolAddress((void**)&WfP,   g_WfP);
    cudaGetSymbolAddress((void**)&WbTP,  g_WbTP);
    cudaGetSymbolAddress((void**)&Wa1P,  g_Wa1P);
    cudaGetSymbolAddress((void**)&Wa2P,  g_Wa2P);

    cudaFuncSetAttribute(gemm_mma<0,0,1>, cudaFuncAttributeMaxDynamicSharedMemorySize, SMEM_GEMM);
    cudaFuncSetAttribute(gemm_mma<1,2,2>, cudaFuncAttributeMaxDynamicSharedMemorySize, SMEM_GEMM);
    cudaFuncSetAttribute(gemm_mma<1,0,3>, cudaFuncAttributeMaxDynamicSharedMemorySize, SMEM_GEMM);
    cudaFuncSetAttribute(gemm_mma<1,0,1>, cudaFuncAttributeMaxDynamicSharedMemorySize, SMEM_GEMM);
    cudaFuncSetAttribute(gemm_mma<1,1,2>, cudaFuncAttributeMaxDynamicSharedMemorySize, SMEM_GEMM);

    const int M = MROWS;                  // 49152, /128 = 384

    // ---- weight prep ----
    fusew_kernel<<<512, 256>>>(W2, Wc, Wf);
    split_kernel<<<1024, 256>>>(W1, W1P, 262144, 262144);
    swab_split<<<1024, 256>>>(Wa, Wb, WabP);
    split_kernel<<<512, 256>>>(Wf, WfP, 131072, 131072);
    tsplit_kernel<<<256, 256>>>(Wbil, WbTP);
    split_kernel<<<1024, 256>>>(Wa1, Wa1P, 262144, 262144);
    split_kernel<<<2048, 256>>>(Wa2, Wa2P, 524288, 524288);

    // ---- encoder (both sides) ----
    for (int t = 0; t < 2; t++) {
        const float* X = t ? tgt : src;
        float* enc = t ? encT : encS;
        gemm_mma<0,0,1><<<dim3(4, 384), 256, SMEM_GEMM>>>(
            X, 0, W1P, 262144, b1, x1, nullptr, 0, M, 256, 1024, 256);
        rmsnorm_planes<<<M / 8, 256>>>(x1, g1, x1P, M);
        gemm_mma<1,2,2><<<dim3(16, 384), 256, SMEM_GEMM>>>(
            x1P, PS_256, WabP, 262144, nullptr, nullptr, hP, PS_512, M, 1024, 256, 512);
        if (t == 0)
            gemm_mma<1,0,3><<<dim3(4, 384), 256, SMEM_GEMM>>>(
                hP, PS_512, WfP, 131072, b2, enc, encSP, PS_256, M, 256, 512, 256);
        else
            gemm_mma<1,0,1><<<dim3(4, 384), 256, SMEM_GEMM>>>(
                hP, PS_512, WfP, 131072, b2, enc, nullptr, 0, M, 256, 512, 256);
    }

    // ---- bilinear u = encS @ Wbil ----
    gemm_mma<1,0,1><<<dim3(4, 384), 256, SMEM_GEMM>>>(
        encSP, PS_256, WbTP, 65536, nullptr, ub, nullptr, 0, M, 256, 256, 256);

    // ---- sinkhorn / mapping / confidence / combined planes ----
    batch_kernel<<<BATCH, 256>>>(ub, encT, encS, bbil, Wc1, bc1,
                                 out + OUT_MAPPING_OFF, out + OUT_MAPPED_OFF,
                                 out + OUT_CONF_OFF, combP);

    // ---- answer projection ----
    gemm_mma<1,1,2><<<dim3(8, 384), 256, SMEM_GEMM>>>(
        combP, PS_512, Wa1P, 262144, ba1, nullptr, bigP, PS_512, M, 512, 512, 512);
    gemm_mma<1,0,1><<<dim3(16, 384), 256, SMEM_GEMM>>>(
        bigP, PS_512, Wa2P, 524288, ba2, out + OUT_ANSWER_OFF, nullptr, 0, M, 1024, 512, 1024);
    rmsnorm_kernel<DDIM><<<M / 8, 256>>>(out + OUT_ANSWER_OFF, g2, M);
}

// round 6
// speedup vs baseline: 2.8392x; 1.0253x over previous
#include <cuda_runtime.h>
#include <cuda_fp16.h>
#include <cstdint>
#include <math.h>

#define BATCH 8192
#define RROLE 6
#define DDIM 1024
#define HDIM 256
#define MROWS (BATCH * RROLE)          // 49152
#define M2 (2 * MROWS)                 // 98304 (src+tgt merged)
#define TEMP_INV 2.0f
#define SINKHORN_ITERS 5

#define OUT_ANSWER_OFF  0
#define OUT_MAPPING_OFF ((size_t)MROWS * DDIM)
#define OUT_MAPPED_OFF  (OUT_MAPPING_OFF + (size_t)BATCH * RROLE * RROLE)
#define OUT_CONF_OFF    (OUT_MAPPED_OFF + (size_t)MROWS * HDIM)

#define WSCALE 1024.0f
#define ISCALE (1.0f / 1024.0f)

// plane strides (elements per plane)
#define PSIN ((size_t)M2 * 1024)
#define PX1  ((size_t)M2 * 256)
#define PH   ((size_t)M2 * 512)
#define PE   ((size_t)M2 * 256)
#define PC   ((size_t)MROWS * 512)

// ---------------- device scratch ----------------
__device__ float g_Wf[HDIM * 2 * HDIM];
__device__ float g_x1[(size_t)M2 * 256];
__device__ float g_enc[(size_t)M2 * 256];          // rows 0..M-1 src, M..2M-1 tgt
__device__ float g_u[(size_t)MROWS * 256];

__device__ __half g_inP  [2 * (size_t)M2 * 1024];  // input planes (src rows then tgt rows)
__device__ __half g_x1P  [2 * (size_t)M2 * 256];
__device__ __half g_hP   [2 * (size_t)M2 * 512];
__device__ __half g_encP [2 * (size_t)M2 * 256];
__device__ __half g_combP[2 * (size_t)MROWS * 512];
__device__ __half g_bigP [2 * (size_t)MROWS * 512];

// fp16 weight planes (2 planes each, scaled by WSCALE)
__device__ __half g_W1P [2 * 256 * 1024];
__device__ __half g_WabP[2 * 1024 * 256];   // interleaved gate/value rows
__device__ __half g_WfP [2 * 256 * 512];
__device__ __half g_WbTP[2 * 256 * 256];
__device__ __half g_Wa1P[2 * 512 * 512];
__device__ __half g_Wa2P[2 * 1024 * 512];

// ---------------- helpers ----------------
__device__ __forceinline__ uint32_t smem_u32(const void* p) {
    uint32_t a;
    asm("{ .reg .u64 t; cvta.to.shared.u64 t, %1; cvt.u32.u64 %0, t; }" : "=r"(a) : "l"(p));
    return a;
}
__device__ __forceinline__ float gelu_tanh(float x) {
    float x3 = x * x * x;
    return 0.5f * x * (1.0f + tanhf(0.7978845608028654f * (x + 0.044715f * x3)));
}
__device__ __forceinline__ void ldsm4(uint32_t& r0, uint32_t& r1, uint32_t& r2, uint32_t& r3,
                                      uint32_t addr) {
    asm volatile("ldmatrix.sync.aligned.m8n8.x4.shared.b16 {%0,%1,%2,%3}, [%4];"
                 : "=r"(r0), "=r"(r1), "=r"(r2), "=r"(r3) : "r"(addr));
}
__device__ __forceinline__ void mma16816(float* c, const uint32_t* a, const uint32_t* b) {
    asm volatile("mma.sync.aligned.m16n8k16.row.col.f32.f16.f16.f32 "
                 "{%0,%1,%2,%3}, {%4,%5,%6,%7}, {%8,%9}, {%0,%1,%2,%3};"
                 : "+f"(c[0]), "+f"(c[1]), "+f"(c[2]), "+f"(c[3])
                 : "r"(a[0]), "r"(a[1]), "r"(a[2]), "r"(a[3]), "r"(b[0]), "r"(b[1]));
}
__device__ __forceinline__ uint32_t packh(float x, float y) {
    __half h0 = __float2half(x), h1 = __float2half(y);
    return (uint32_t)__half_as_ushort(h0) | ((uint32_t)__half_as_ushort(h1) << 16);
}
#define CP_ASYNC16(dst, src) \
    asm volatile("cp.async.cg.shared.global [%0], [%1], 16;" :: "r"(dst), "l"(src) : "memory")
#define CP_COMMIT() asm volatile("cp.async.commit_group;" ::: "memory")
#define CP_WAIT1()  asm volatile("cp.async.wait_group 1;" ::: "memory")

// ---------------- HMMA GEMM (3-stage pipelined) ----------------
// C[M,Nout] = act((Aplanes @ Bplanes^T) * ISCALE + bias)
// A: 2 fp16 planes [M,K] (hi @0, lo @aPstride). B: 2 planes [N,K] (scaled WSCALE).
// ACT: 0 none, 1 gelu, 2 swiglu (B rows interleaved 32 gate + 32 value per 64)
// OUTMODE bit0: fp32 Cf; bit1: fp16 planes Cp (hi @0, lo @cPstride)
// BM=128, BN=64, BK=32. 256 threads, 8 warps (4m x 2n), warp tile 32x32.
// stage layout (bytes): Ah 0..10240, Al 10240..20480, Bh 20480..25600, Bl 25600..30720
#define STG 30720
#define SMEM_GEMM (3 * STG)   // 92160

template <int ACT, int OUTMODE>
__global__ __launch_bounds__(256, 2) void gemm_mma(
    const __half* __restrict__ Ap, size_t aPstride,
    const __half* __restrict__ Bp, size_t bPstride,
    const float* __restrict__ bias,
    float* __restrict__ Cf,
    __half* __restrict__ Cp, size_t cPstride,
    int N, int K, int Nout)
{
    extern __shared__ char smem[];
    const uint32_t sb = smem_u32(smem);
    const int tid = threadIdx.x, lane = tid & 31, wid = tid >> 5;
    const int bm = blockIdx.y * 128, bn = blockIdx.x * 64;
    const int wm = (wid >> 1) * 32, wn = (wid & 1) * 32;

    const uint32_t aLd0 = sb + (uint32_t)((wm + (lane & 15)) * 80 + (lane >> 4) * 16);
    const uint32_t bLd0 = sb + 20480u +
        (uint32_t)(((wn + (lane & 7) + ((lane >> 4) & 1) * 8) * 80) + ((lane >> 3) & 1) * 16);

    float acc[2][4][4];
#pragma unroll
    for (int mt = 0; mt < 2; mt++)
#pragma unroll
        for (int nt = 0; nt < 4; nt++)
#pragma unroll
            for (int i = 0; i < 4; i++) acc[mt][nt][i] = 0.0f;

    const int nkb = K >> 5;

    auto issue = [&](int kidx, uint32_t base) {
#pragma unroll
        for (int t = 0; t < 4; t++) {
            int idx = t * 256 + tid;
            int pl = idx >> 9, row = (idx >> 2) & 127, s = idx & 3;
            const __half* srcp = Ap + (size_t)pl * aPstride + (size_t)(bm + row) * K
                                 + kidx * 32 + s * 8;
            CP_ASYNC16(base + pl * 10240u + row * 80u + s * 16u, srcp);
        }
#pragma unroll
        for (int t = 0; t < 2; t++) {
            int idx = t * 256 + tid;
            int pl = idx >> 8, row = (idx >> 2) & 63, s = idx & 3;
            const __half* srcp = Bp + (size_t)pl * bPstride + (size_t)(bn + row) * K
                                 + kidx * 32 + s * 8;
            CP_ASYNC16(base + 20480u + pl * 5120u + row * 80u + s * 16u, srcp);
        }
    };

    // prologue: stages 0 and 1
    issue(0, sb);
    CP_COMMIT();
    if (nkb > 1) issue(1, sb + STG);
    CP_COMMIT();

    uint32_t curStage = 0;
    for (int kb = 0; kb < nkb; kb++) {
        CP_WAIT1();
        __syncthreads();
        const uint32_t cur = curStage * STG;
        uint32_t nxtStage = curStage + 2;
        if (nxtStage >= 3) nxtStage -= 3;
        if (kb + 2 < nkb) issue(kb + 2, sb + nxtStage * STG);
        CP_COMMIT();
        curStage = (curStage + 1 == 3) ? 0 : curStage + 1;

#pragma unroll
        for (int ks = 0; ks < 2; ks++) {
            uint32_t af[2][2][4];
#pragma unroll
            for (int mt = 0; mt < 2; mt++)
#pragma unroll
                for (int pl = 0; pl < 2; pl++)
                    ldsm4(af[mt][pl][0], af[mt][pl][1], af[mt][pl][2], af[mt][pl][3],
                          aLd0 + cur + pl * 10240u + mt * 16 * 80 + ks * 32);
            uint32_t bf[2][4][2];
#pragma unroll
            for (int pl = 0; pl < 2; pl++)
#pragma unroll
                for (int nt2 = 0; nt2 < 2; nt2++) {
                    uint32_t r0, r1, r2, r3;
                    ldsm4(r0, r1, r2, r3,
                          bLd0 + cur + pl * 5120u + nt2 * 16 * 80 + ks * 32);
                    bf[pl][nt2 * 2][0] = r0; bf[pl][nt2 * 2][1] = r1;
                    bf[pl][nt2 * 2 + 1][0] = r2; bf[pl][nt2 * 2 + 1][1] = r3;
                }
#pragma unroll
            for (int prod = 0; prod < 3; prod++) {
                const int apl = (prod == 2) ? 1 : 0;
                const int bpl = (prod == 1) ? 1 : 0;
#pragma unroll
                for (int mt = 0; mt < 2; mt++)
#pragma unroll
                    for (int nt = 0; nt < 4; nt++)
                        mma16816(acc[mt][nt], af[mt][apl], bf[bpl][nt]);
            }
        }
    }

    // ---- epilogue ----
    if (ACT == 2) {
        __syncthreads();   // protect stage buffers until all warps finish MMAs
        float* vs = (float*)smem;
        if (wn == 32) {
#pragma unroll
            for (int mt = 0; mt < 2; mt++)
#pragma unroll
                for (int nt = 0; nt < 4; nt++) {
                    int r0 = wm + mt * 16 + (lane >> 2);
                    int c = nt * 8 + (lane & 3) * 2;
                    vs[r0 * 34 + c]           = acc[mt][nt][0] * ISCALE;
                    vs[r0 * 34 + c + 1]       = acc[mt][nt][1] * ISCALE;
                    vs[(r0 + 8) * 34 + c]     = acc[mt][nt][2] * ISCALE;
                    vs[(r0 + 8) * 34 + c + 1] = acc[mt][nt][3] * ISCALE;
                }
        }
        __syncthreads();
        if (wn == 0) {
#pragma unroll
            for (int mt = 0; mt < 2; mt++) {
                int r0 = wm + mt * 16 + (lane >> 2);
#pragma unroll
                for (int nt = 0; nt < 4; nt++) {
                    int c = nt * 8 + (lane & 3) * 2;
                    float g0 = acc[mt][nt][0] * ISCALE, g1 = acc[mt][nt][1] * ISCALE;
                    float g2 = acc[mt][nt][2] * ISCALE, g3 = acc[mt][nt][3] * ISCALE;
                    float o0 = g0 / (1.0f + expf(-g0)) * vs[r0 * 34 + c];
                    float o1 = g1 / (1.0f + expf(-g1)) * vs[r0 * 34 + c + 1];
                    float o2 = g2 / (1.0f + expf(-g2)) * vs[(r0 + 8) * 34 + c];
                    float o3 = g3 / (1.0f + expf(-g3)) * vs[(r0 + 8) * 34 + c + 1];
                    size_t row = (size_t)(bm + r0);
                    int col = (bn >> 1) + c;
                    __half h0 = __float2half(o0), h1 = __float2half(o1);
                    __half h2 = __float2half(o2), h3 = __float2half(o3);
                    *(uint32_t*)(Cp + row * Nout + col) =
                        (uint32_t)__half_as_ushort(h0) | ((uint32_t)__half_as_ushort(h1) << 16);
                    *(uint32_t*)(Cp + cPstride + row * Nout + col) =
                        packh(o0 - __half2float(h0), o1 - __half2float(h1));
                    *(uint32_t*)(Cp + (row + 8) * Nout + col) =
                        (uint32_t)__half_as_ushort(h2) | ((uint32_t)__half_as_ushort(h3) << 16);
                    *(uint32_t*)(Cp + cPstride + (row + 8) * Nout + col) =
                        packh(o2 - __half2float(h2), o3 - __half2float(h3));
                }
            }
        }
        return;
    }

#pragma unroll
    for (int mt = 0; mt < 2; mt++) {
        int row0 = bm + wm + mt * 16 + (lane >> 2);
#pragma unroll
        for (int nt = 0; nt < 4; nt++) {
            int col0 = bn + wn + nt * 8 + (lane & 3) * 2;
            float b0 = 0.f, b1 = 0.f;
            if (bias) { b0 = bias[col0]; b1 = bias[col0 + 1]; }
            float o0 = acc[mt][nt][0] * ISCALE + b0;
            float o1 = acc[mt][nt][1] * ISCALE + b1;
            float o2 = acc[mt][nt][2] * ISCALE + b0;
            float o3 = acc[mt][nt][3] * ISCALE + b1;
            if (ACT == 1) {
                o0 = gelu_tanh(o0); o1 = gelu_tanh(o1);
                o2 = gelu_tanh(o2); o3 = gelu_tanh(o3);
            }
            if (OUTMODE & 1) {
                *(float2*)(Cf + (size_t)row0 * Nout + col0) = make_float2(o0, o1);
                *(float2*)(Cf + (size_t)(row0 + 8) * Nout + col0) = make_float2(o2, o3);
            }
            if (OUTMODE & 2) {
                __half h0 = __float2half(o0), h1 = __float2half(o1);
                __half h2 = __float2half(o2), h3 = __float2half(o3);
                *(uint32_t*)(Cp + (size_t)row0 * Nout + col0) =
                    (uint32_t)__half_as_ushort(h0) | ((uint32_t)__half_as_ushort(h1) << 16);
                *(uint32_t*)(Cp + cPstride + (size_t)row0 * Nout + col0) =
                    packh(o0 - __half2float(h0), o1 - __half2float(h1));
                *(uint32_t*)(Cp + (size_t)(row0 + 8) * Nout + col0) =
                    (uint32_t)__half_as_ushort(h2) | ((uint32_t)__half_as_ushort(h3) << 16);
                *(uint32_t*)(Cp + cPstride + (size_t)(row0 + 8) * Nout + col0) =
                    packh(o2 - __half2float(h2), o3 - __half2float(h3));
            }
        }
    }
}

// ---------------- input split: src+tgt fp32 -> 2 fp16 planes ----------------
__global__ void insplit(const float4* __restrict__ src4, const float4* __restrict__ tgt4,
                        __half* __restrict__ out)
{
    size_t i = (size_t)blockIdx.x * 256 + threadIdx.x;    // float4 index over M2*256
    const size_t half4 = (size_t)MROWS * 256;
    float4 f = (i < half4) ? src4[i] : tgt4[i - half4];
    float v[4] = {f.x, f.y, f.z, f.w};
    uint32_t hp[2], lp[2];
#pragma unroll
    for (int j = 0; j < 2; j++) {
        __half h0 = __float2half(v[2 * j]), h1 = __float2half(v[2 * j + 1]);
        hp[j] = (uint32_t)__half_as_ushort(h0) | ((uint32_t)__half_as_ushort(h1) << 16);
        lp[j] = packh(v[2 * j] - __half2float(h0), v[2 * j + 1] - __half2float(h1));
    }
    *(uint2*)(out + 4 * i) = make_uint2(hp[0], hp[1]);
    *(uint2*)(out + PSIN + 4 * i) = make_uint2(lp[0], lp[1]);
}

// ---------------- weight prep ----------------
__global__ void split_kernel(const float* __restrict__ W, __half* __restrict__ out,
                             int n, int pstride)
{
    int i = blockIdx.x * 256 + threadIdx.x;
    if (i >= n) return;
    float r = W[i] * WSCALE;
    __half h = __float2half(r);
    out[i] = h;
    r -= __half2float(h);
    out[(size_t)pstride + i] = __float2half(r);
}

__global__ void swab_split(const float* __restrict__ Wa, const float* __restrict__ Wb,
                           __half* __restrict__ out)
{
    int i = blockIdx.x * 256 + threadIdx.x;   // 262144
    int nrow = i >> 8, k = i & 255;
    int j = nrow >> 6, r = nrow & 63;
    float w = (r < 32) ? Wa[(j * 32 + r) * 256 + k] : Wb[(j * 32 + r - 32) * 256 + k];
    float rr = w * WSCALE;
    __half h = __float2half(rr);
    out[i] = h;
    rr -= __half2float(h);
    out[262144 + i] = __float2half(rr);
}

__global__ void tsplit_kernel(const float* __restrict__ W, __half* __restrict__ out)
{
    int i = blockIdx.x * 256 + threadIdx.x;
    int nrow = i >> 8, k = i & 255;
    float r = W[k * 256 + nrow] * WSCALE;
    __half h = __float2half(r);
    out[i] = h;
    r -= __half2float(h);
    out[65536 + i] = __float2half(r);
}

__global__ void fusew_kernel(const float* __restrict__ W2, const float* __restrict__ Wc,
                             float* __restrict__ Wf)
{
    int idx = blockIdx.x * blockDim.x + threadIdx.x;
    int i = idx >> 9, j = idx & 511;
    float s = 0.0f;
    for (int k = 0; k < 256; k++) s += W2[i * 256 + k] * Wc[k * 512 + j];
    Wf[idx] = s;
}

// ---------------- elementwise ----------------
template <int NC>
__global__ void rmsnorm_kernel(float* __restrict__ x, const float* __restrict__ g, int rows)
{
    int row = blockIdx.x * 8 + (threadIdx.x >> 5);
    int lane = threadIdx.x & 31;
    if (row >= rows) return;
    float* p = x + (size_t)row * NC;
    constexpr int V = NC / 32;
    float v[V];
    float ss = 0.0f;
#pragma unroll
    for (int i = 0; i < V; i++) { v[i] = p[lane + 32 * i]; ss += v[i] * v[i]; }
#pragma unroll
    for (int o = 16; o > 0; o >>= 1) ss += __shfl_xor_sync(0xffffffffu, ss, o);
    float sc = rsqrtf(ss * (1.0f / NC) + 1e-6f);
#pragma unroll
    for (int i = 0; i < V; i++) p[lane + 32 * i] = v[i] * sc * g[lane + 32 * i];
}

// rmsnorm reading fp32, writing fp16 planes (N=256)
__global__ void rmsnorm_planes(const float* __restrict__ x, const float* __restrict__ g,
                               __half* __restrict__ out, int rows)
{
    int row = blockIdx.x * 8 + (threadIdx.x >> 5);
    int lane = threadIdx.x & 31;
    if (row >= rows) return;
    const float* p = x + (size_t)row * 256;
    float v[8];
    float ss = 0.0f;
#pragma unroll
    for (int i = 0; i < 8; i++) { v[i] = p[lane + 32 * i]; ss += v[i] * v[i]; }
#pragma unroll
    for (int o = 16; o > 0; o >>= 1) ss += __shfl_xor_sync(0xffffffffu, ss, o);
    float sc = rsqrtf(ss * (1.0f / 256.0f) + 1e-6f);
#pragma unroll
    for (int i = 0; i < 8; i++) {
        float o = v[i] * sc * g[lane + 32 * i];
        __half h = __float2half(o);
        out[(size_t)row * 256 + lane + 32 * i] = h;
        out[PX1 + (size_t)row * 256 + lane + 32 * i] = __float2half(o - __half2float(h));
    }
}

// ---------------- per-batch sinkhorn etc ----------------
__global__ __launch_bounds__(256) void batch_kernel(
    const float* __restrict__ u, const float* __restrict__ tgt,
    const float* __restrict__ src, const float* __restrict__ bbil,
    const float* __restrict__ Wc1, const float* __restrict__ bc1,
    float* __restrict__ out_mapping, float* __restrict__ out_mapped,
    float* __restrict__ out_conf, __half* __restrict__ combP)
{
    const int b = blockIdx.x;
    const int tid = threadIdx.x;
    __shared__ float u_s[RROLE * HDIM];
    __shared__ float t_s[RROLE * HDIM];
    __shared__ float s_s[RROLE * HDIM];
    __shared__ float la[RROLE * RROLE];
    __shared__ float map_s[RROLE * RROLE];
    __shared__ float lse[RROLE];
    __shared__ float red[256];

    const size_t base = (size_t)b * RROLE * HDIM;
    for (int e = tid; e < RROLE * HDIM; e += 256) {
        u_s[e] = u[base + e];
        t_s[e] = tgt[base + e];
        s_s[e] = src[base + e];
    }
    __syncthreads();

    const float bb = bbil[0];
    const int warp = tid >> 5, lane = tid & 31;
    for (int p = warp; p < RROLE * RROLE; p += 8) {
        int i = p / RROLE, j = p % RROLE;
        float d = 0.0f;
        for (int h = lane; h < HDIM; h += 32) d += u_s[i * HDIM + h] * t_s[j * HDIM + h];
#pragma unroll
        for (int o = 16; o > 0; o >>= 1) d += __shfl_xor_sync(0xffffffffu, d, o);
        if (lane == 0) la[p] = (d + bb) * TEMP_INV;
    }
    __syncthreads();

    for (int it = 0; it < SINKHORN_ITERS; it++) {
        if (tid < RROLE) {
            float m = -1e30f;
            for (int j = 0; j < RROLE; j++) m = fmaxf(m, la[tid * RROLE + j]);
            float s = 0.0f;
            for (int j = 0; j < RROLE; j++) s += expf(la[tid * RROLE + j] - m);
            lse[tid] = m + logf(s);
        }
        __syncthreads();
        if (tid < RROLE * RROLE) la[tid] -= lse[tid / RROLE];
        __syncthreads();
        if (tid < RROLE) {
            float m = -1e30f;
            for (int i = 0; i < RROLE; i++) m = fmaxf(m, la[i * RROLE + tid]);
            float s = 0.0f;
            for (int i = 0; i < RROLE; i++) s += expf(la[i * RROLE + tid] - m);
            lse[tid] = m + logf(s);
        }
        __syncthreads();
        if (tid < RROLE * RROLE) la[tid] -= lse[tid % RROLE];
        __syncthreads();
    }

    if (tid < RROLE * RROLE) {
        float mv = expf(la[tid]);
        map_s[tid] = mv;
        out_mapping[(size_t)b * RROLE * RROLE + tid] = mv;
    }
    __syncthreads();

    float local = 0.0f;
    for (int e = tid; e < RROLE * HDIM; e += 256) {
        int i = e >> 8;
        int h = e & 255;
        float v = 0.0f;
#pragma unroll
        for (int j = 0; j < RROLE; j++) v += map_s[i * RROLE + j] * t_s[j * HDIM + h];
        out_mapped[base + e] = v;
        size_t cbase = ((size_t)b * RROLE + i) * 512;
        __half vh = __float2half(v);
        combP[cbase + h] = vh;
        combP[PC + cbase + h] = __float2half(v - __half2float(vh));
        float t = t_s[i * HDIM + h];
        __half th = __float2half(t);
        combP[cbase + 256 + h] = th;
        combP[PC + cbase + 256 + h] = __float2half(t - __half2float(th));
        local += fabsf(v - s_s[e]);
    }
    red[tid] = local;
    __syncthreads();
    for (int s = 128; s > 0; s >>= 1) {
        if (tid < s) red[tid] += red[tid + s];
        __syncthreads();
    }
    if (tid == 0) {
        float conf_in = red[0] * (1.0f / (RROLE * HDIM));
        float z = conf_in * Wc1[0] + bc1[0];
        out_conf[b] = 1.0f / (1.0f + expf(-z));
    }
}

// ---------------- launch ----------------
extern "C" void kernel_launch(void* const* d_in, const int* in_sizes, int n_in,
                              void* d_out, int out_size)
{
    (void)in_sizes; (void)n_in; (void)out_size;
    const float* src  = (const float*)d_in[0];
    const float* tgt  = (const float*)d_in[1];
    const float* W1   = (const float*)d_in[2];
    const float* b1   = (const float*)d_in[3];
    const float* g1   = (const float*)d_in[4];
    const float* Wa   = (const float*)d_in[5];
    const float* Wb   = (const float*)d_in[6];
    const float* Wc   = (const float*)d_in[7];
    const float* W2   = (const float*)d_in[8];
    const float* b2   = (const float*)d_in[9];
    const float* Wbil = (const float*)d_in[10];
    const float* bbil = (const float*)d_in[11];
    const float* Wa1  = (const float*)d_in[12];
    const float* ba1  = (const float*)d_in[13];
    const float* Wa2  = (const float*)d_in[14];
    const float* ba2  = (const float*)d_in[15];
    const float* g2   = (const float*)d_in[16];
    const float* Wc1  = (const float*)d_in[17];
    const float* bc1  = (const float*)d_in[18];
    float* out = (float*)d_out;

    float *Wf, *x1, *enc, *ub;
    __half *inP, *x1P, *hP, *encP, *combP, *bigP;
    __half *W1P, *WabP, *WfP, *WbTP, *Wa1P, *Wa2P;
    cudaGetSymbolAddress((void**)&Wf,    g_Wf);
    cudaGetSymbolAddress((void**)&x1,    g_x1);
    cudaGetSymbolAddress((void**)&enc,   g_enc);
    cudaGetSymbolAddress((void**)&ub,    g_u);
    cudaGetSymbolAddress((void**)&inP,   g_inP);
    cudaGetSymbolAddress((void**)&x1P,   g_x1P);
    cudaGetSymbolAddress((void**)&hP,    g_hP);
    cudaGetSymbolAddress((void**)&encP,  g_encP);
    cudaGetSymbolAddress((void**)&combP, g_combP);
    cudaGetSymbolAddress((void**)&bigP,  g_bigP);
    cudaGetSymbolAddress((void**)&W1P,   g_W1P);
    cudaGetSymbolAddress((void**)&WabP,  g_WabP);
    cudaGetSymbolAddress((void**)&WfP,   g_WfP);
    cudaGetSymbolAddress((void**)&WbTP,  g_WbTP);
    cudaGetSymbolAddress((void**)&Wa1P,  g_Wa1P);
    cudaGetSymbolAddress((void**)&Wa2P,  g_Wa2P);

    cudaFuncSetAttribute(gemm_mma<0,1>, cudaFuncAttributeMaxDynamicSharedMemorySize, SMEM_GEMM);
    cudaFuncSetAttribute(gemm_mma<0,3>, cudaFuncAttributeMaxDynamicSharedMemorySize, SMEM_GEMM);
    cudaFuncSetAttribute(gemm_mma<2,2>, cudaFuncAttributeMaxDynamicSharedMemorySize, SMEM_GEMM);
    cudaFuncSetAttribute(gemm_mma<1,2>, cudaFuncAttributeMaxDynamicSharedMemorySize, SMEM_GEMM);

    // ---- prep ----
    fusew_kernel<<<512, 256>>>(W2, Wc, Wf);
    split_kernel<<<1024, 256>>>(W1, W1P, 262144, 262144);
    swab_split<<<1024, 256>>>(Wa, Wb, WabP);
    split_kernel<<<512, 256>>>(Wf, WfP, 131072, 131072);
    tsplit_kernel<<<256, 256>>>(Wbil, WbTP);
    split_kernel<<<1024, 256>>>(Wa1, Wa1P, 262144, 262144);
    split_kernel<<<2048, 256>>>(Wa2, Wa2P, 524288, 524288);
    insplit<<<M2 * 256 / 256, 256>>>((const float4*)src, (const float4*)tgt, inP);

    // ---- merged encoder (src rows 0..M-1, tgt rows M..2M-1) ----
    gemm_mma<0,1><<<dim3(4, M2 / 128), 256, SMEM_GEMM>>>(
        inP, PSIN, W1P, 262144, b1, x1, nullptr, 0, 256, 1024, 256);
    rmsnorm_planes<<<M2 / 8, 256>>>(x1, g1, x1P, M2);
    gemm_mma<2,2><<<dim3(16, M2 / 128), 256, SMEM_GEMM>>>(
        x1P, PX1, WabP, 262144, nullptr, nullptr, hP, PH, 1024, 256, 512);
    gemm_mma<0,3><<<dim3(4, M2 / 128), 256, SMEM_GEMM>>>(
        hP, PH, WfP, 131072, b2, enc, encP, PE, 256, 512, 256);

    // ---- bilinear u = enc_src @ Wbil (first MROWS rows of encP) ----
    gemm_mma<0,1><<<dim3(4, MROWS / 128), 256, SMEM_GEMM>>>(
        encP, PE, WbTP, 65536, nullptr, ub, nullptr, 0, 256, 256, 256);

    // ---- sinkhorn / mapping / confidence / combined planes ----
    batch_kernel<<<BATCH, 256>>>(ub, enc + (size_t)MROWS * 256, enc, bbil, Wc1, bc1,
                                 out + OUT_MAPPING_OFF, out + OUT_MAPPED_OFF,
                                 out + OUT_CONF_OFF, combP);

    // ---- answer projection ----
    gemm_mma<1,2><<<dim3(8, MROWS / 128), 256, SMEM_GEMM>>>(
        combP, PC, Wa1P, 262144, ba1, nullptr, bigP, PC, 512, 512, 512);
    gemm_mma<0,1><<<dim3(16, MROWS / 128), 256, SMEM_GEMM>>>(
        bigP, PC, Wa2P, 524288, ba2, out + OUT_ANSWER_OFF, nullptr, 0, 1024, 512, 1024);
    rmsnorm_kernel<DDIM><<<MROWS / 8, 256>>>(out + OUT_ANSWER_OFF, g2, MROWS);
}

// round 7
// speedup vs baseline: 3.1481x; 1.1088x over previous
#include <cuda_runtime.h>
#include <cuda_fp16.h>
#include <cstdint>
#include <math.h>

#define BATCH 8192
#define RROLE 6
#define DDIM 1024
#define HDIM 256
#define MROWS (BATCH * RROLE)          // 49152
#define M2 (2 * MROWS)                 // 98304 (src+tgt merged)
#define TEMP_INV 2.0f
#define SINKHORN_ITERS 5

#define OUT_ANSWER_OFF  0
#define OUT_MAPPING_OFF ((size_t)MROWS * DDIM)
#define OUT_MAPPED_OFF  (OUT_MAPPING_OFF + (size_t)BATCH * RROLE * RROLE)
#define OUT_CONF_OFF    (OUT_MAPPED_OFF + (size_t)MROWS * HDIM)

#define WSCALE 1024.0f
#define ISCALE (1.0f / 1024.0f)

// plane strides (elements per plane)
#define PSIN ((size_t)M2 * 1024)
#define PX1  ((size_t)M2 * 256)
#define PH   ((size_t)M2 * 512)
#define PE   ((size_t)M2 * 256)
#define PC   ((size_t)MROWS * 512)

// ---------------- device scratch ----------------
__device__ float g_Wf[HDIM * 2 * HDIM];
__device__ float g_x1[(size_t)M2 * 256];
__device__ float g_enc[(size_t)M2 * 256];          // rows 0..M-1 src, M..2M-1 tgt
__device__ float g_u[(size_t)MROWS * 256];

__device__ __half g_inP  [2 * (size_t)M2 * 1024];  // input planes (src rows then tgt rows)
__device__ __half g_x1P  [2 * (size_t)M2 * 256];
__device__ __half g_hP   [2 * (size_t)M2 * 512];
__device__ __half g_encP [2 * (size_t)M2 * 256];
__device__ __half g_combP[(size_t)MROWS * 512];    // hi plane only (answer path 2-prod)
__device__ __half g_bigP [(size_t)MROWS * 512];    // hi plane only

// fp16 weight planes (2 planes each, scaled by WSCALE)
__device__ __half g_W1P [2 * 256 * 1024];
__device__ __half g_WabP[2 * 1024 * 256];   // interleaved gate/value rows
__device__ __half g_WfP [2 * 256 * 512];
__device__ __half g_WbTP[2 * 256 * 256];
__device__ __half g_Wa1P[2 * 512 * 512];
__device__ __half g_Wa2P[2 * 1024 * 512];

// ---------------- helpers ----------------
__device__ __forceinline__ uint32_t smem_u32(const void* p) {
    uint32_t a;
    asm("{ .reg .u64 t; cvta.to.shared.u64 t, %1; cvt.u32.u64 %0, t; }" : "=r"(a) : "l"(p));
    return a;
}
__device__ __forceinline__ float gelu_tanh(float x) {
    float x3 = x * x * x;
    return 0.5f * x * (1.0f + tanhf(0.7978845608028654f * (x + 0.044715f * x3)));
}
__device__ __forceinline__ void ldsm4(uint32_t& r0, uint32_t& r1, uint32_t& r2, uint32_t& r3,
                                      uint32_t addr) {
    asm volatile("ldmatrix.sync.aligned.m8n8.x4.shared.b16 {%0,%1,%2,%3}, [%4];"
                 : "=r"(r0), "=r"(r1), "=r"(r2), "=r"(r3) : "r"(addr));
}
__device__ __forceinline__ void mma16816(float* c, const uint32_t* a, const uint32_t* b) {
    asm volatile("mma.sync.aligned.m16n8k16.row.col.f32.f16.f16.f32 "
                 "{%0,%1,%2,%3}, {%4,%5,%6,%7}, {%8,%9}, {%0,%1,%2,%3};"
                 : "+f"(c[0]), "+f"(c[1]), "+f"(c[2]), "+f"(c[3])
                 : "r"(a[0]), "r"(a[1]), "r"(a[2]), "r"(a[3]), "r"(b[0]), "r"(b[1]));
}
__device__ __forceinline__ uint32_t packh(float x, float y) {
    __half h0 = __float2half(x), h1 = __float2half(y);
    return (uint32_t)__half_as_ushort(h0) | ((uint32_t)__half_as_ushort(h1) << 16);
}
#define CP_ASYNC16(dst, src) \
    asm volatile("cp.async.cg.shared.global [%0], [%1], 16;" :: "r"(dst), "l"(src) : "memory")
#define CP_COMMIT() asm volatile("cp.async.commit_group;" ::: "memory")
#define CP_WAIT1()  asm volatile("cp.async.wait_group 1;" ::: "memory")

// ---------------- HMMA GEMM (3-stage pipelined) ----------------
// C[M,Nout] = act((Aplanes @ Bplanes^T) * ISCALE + bias)
// NPROD=3: A 2 planes (hi,lo), products hh+hl+lh.
// NPROD=2: A hi plane only, products hh+hl (B still 2 planes).
// ACT: 0 none, 1 gelu, 2 swiglu (B rows interleaved 32 gate + 32 value per 64)
// OUTMODE bit0: fp32 Cf; bit1: fp16 planes hi+lo; bit2: fp16 hi plane only
// BM=128, BN=64, BK=32. 256 threads, 8 warps (4m x 2n), warp tile 32x32.
template <int ACT, int OUTMODE, int NPROD>
__global__ __launch_bounds__(256, 2) void gemm_mma(
    const __half* __restrict__ Ap, size_t aPstride,
    const __half* __restrict__ Bp, size_t bPstride,
    const float* __restrict__ bias,
    float* __restrict__ Cf,
    __half* __restrict__ Cp, size_t cPstride,
    int N, int K, int Nout)
{
    constexpr int A_PL = (NPROD == 3) ? 2 : 1;
    constexpr uint32_t ASZ = A_PL * 10240u;
    constexpr uint32_t STG_SZ = ASZ + 10240u;

    extern __shared__ char smem[];
    const uint32_t sb = smem_u32(smem);
    const int tid = threadIdx.x, lane = tid & 31, wid = tid >> 5;
    const int bm = blockIdx.y * 128, bn = blockIdx.x * 64;
    const int wm = (wid >> 1) * 32, wn = (wid & 1) * 32;

    const uint32_t aLd0 = sb + (uint32_t)((wm + (lane & 15)) * 80 + (lane >> 4) * 16);
    const uint32_t bLd0 = sb + ASZ +
        (uint32_t)(((wn + (lane & 7) + ((lane >> 4) & 1) * 8) * 80) + ((lane >> 3) & 1) * 16);

    float acc[2][4][4];
#pragma unroll
    for (int mt = 0; mt < 2; mt++)
#pragma unroll
        for (int nt = 0; nt < 4; nt++)
#pragma unroll
            for (int i = 0; i < 4; i++) acc[mt][nt][i] = 0.0f;

    const int nkb = K >> 5;

    auto issue = [&](int kidx, uint32_t base) {
#pragma unroll
        for (int t = 0; t < 2 * A_PL; t++) {
            int idx = t * 256 + tid;
            int pl = idx >> 9, row = (idx >> 2) & 127, s = idx & 3;
            const __half* srcp = Ap + (size_t)pl * aPstride + (size_t)(bm + row) * K
                                 + kidx * 32 + s * 8;
            CP_ASYNC16(base + pl * 10240u + row * 80u + s * 16u, srcp);
        }
#pragma unroll
        for (int t = 0; t < 2; t++) {
            int idx = t * 256 + tid;
            int pl = idx >> 8, row = (idx >> 2) & 63, s = idx & 3;
            const __half* srcp = Bp + (size_t)pl * bPstride + (size_t)(bn + row) * K
                                 + kidx * 32 + s * 8;
            CP_ASYNC16(base + ASZ + pl * 5120u + row * 80u + s * 16u, srcp);
        }
    };

    // prologue: stages 0 and 1
    issue(0, sb);
    CP_COMMIT();
    if (nkb > 1) issue(1, sb + STG_SZ);
    CP_COMMIT();

    uint32_t curStage = 0;
    for (int kb = 0; kb < nkb; kb++) {
        CP_WAIT1();
        __syncthreads();
        const uint32_t cur = curStage * STG_SZ;
        uint32_t nxtStage = curStage + 2;
        if (nxtStage >= 3) nxtStage -= 3;
        if (kb + 2 < nkb) issue(kb + 2, sb + nxtStage * STG_SZ);
        CP_COMMIT();
        curStage = (curStage + 1 == 3) ? 0 : curStage + 1;

#pragma unroll
        for (int ks = 0; ks < 2; ks++) {
            uint32_t af[2][A_PL][4];
#pragma unroll
            for (int mt = 0; mt < 2; mt++)
#pragma unroll
                for (int pl = 0; pl < A_PL; pl++)
                    ldsm4(af[mt][pl][0], af[mt][pl][1], af[mt][pl][2], af[mt][pl][3],
                          aLd0 + cur + pl * 10240u + mt * 16 * 80 + ks * 32);
            uint32_t bf[2][4][2];
#pragma unroll
            for (int pl = 0; pl < 2; pl++)
#pragma unroll
                for (int nt2 = 0; nt2 < 2; nt2++) {
                    uint32_t r0, r1, r2, r3;
                    ldsm4(r0, r1, r2, r3,
                          bLd0 + cur + pl * 5120u + nt2 * 16 * 80 + ks * 32);
                    bf[pl][nt2 * 2][0] = r0; bf[pl][nt2 * 2][1] = r1;
                    bf[pl][nt2 * 2 + 1][0] = r2; bf[pl][nt2 * 2 + 1][1] = r3;
                }
#pragma unroll
            for (int prod = 0; prod < NPROD; prod++) {
                const int apl = (prod == 2) ? 1 : 0;
                const int bpl = (prod == 1) ? 1 : 0;
#pragma unroll
                for (int mt = 0; mt < 2; mt++)
#pragma unroll
                    for (int nt = 0; nt < 4; nt++)
                        mma16816(acc[mt][nt], af[mt][apl], bf[bpl][nt]);
            }
        }
    }

    // ---- epilogue ----
    if (ACT == 2) {
        __syncthreads();
        float* vs = (float*)smem;
        if (wn == 32) {
#pragma unroll
            for (int mt = 0; mt < 2; mt++)
#pragma unroll
                for (int nt = 0; nt < 4; nt++) {
                    int r0 = wm + mt * 16 + (lane >> 2);
                    int c = nt * 8 + (lane & 3) * 2;
                    vs[r0 * 34 + c]           = acc[mt][nt][0] * ISCALE;
                    vs[r0 * 34 + c + 1]       = acc[mt][nt][1] * ISCALE;
                    vs[(r0 + 8) * 34 + c]     = acc[mt][nt][2] * ISCALE;
                    vs[(r0 + 8) * 34 + c + 1] = acc[mt][nt][3] * ISCALE;
                }
        }
        __syncthreads();
        if (wn == 0) {
#pragma unroll
            for (int mt = 0; mt < 2; mt++) {
                int r0 = wm + mt * 16 + (lane >> 2);
#pragma unroll
                for (int nt = 0; nt < 4; nt++) {
                    int c = nt * 8 + (lane & 3) * 2;
                    float g0 = acc[mt][nt][0] * ISCALE, g1 = acc[mt][nt][1] * ISCALE;
                    float g2 = acc[mt][nt][2] * ISCALE, g3 = acc[mt][nt][3] * ISCALE;
                    float o0 = g0 / (1.0f + expf(-g0)) * vs[r0 * 34 + c];
                    float o1 = g1 / (1.0f + expf(-g1)) * vs[r0 * 34 + c + 1];
                    float o2 = g2 / (1.0f + expf(-g2)) * vs[(r0 + 8) * 34 + c];
                    float o3 = g3 / (1.0f + expf(-g3)) * vs[(r0 + 8) * 34 + c + 1];
                    size_t row = (size_t)(bm + r0);
                    int col = (bn >> 1) + c;
                    __half h0 = __float2half(o0), h1 = __float2half(o1);
                    __half h2 = __float2half(o2), h3 = __float2half(o3);
                    *(uint32_t*)(Cp + row * Nout + col) =
                        (uint32_t)__half_as_ushort(h0) | ((uint32_t)__half_as_ushort(h1) << 16);
                    *(uint32_t*)(Cp + cPstride + row * Nout + col) =
                        packh(o0 - __half2float(h0), o1 - __half2float(h1));
                    *(uint32_t*)(Cp + (row + 8) * Nout + col) =
                        (uint32_t)__half_as_ushort(h2) | ((uint32_t)__half_as_ushort(h3) << 16);
                    *(uint32_t*)(Cp + cPstride + (row + 8) * Nout + col) =
                        packh(o2 - __half2float(h2), o3 - __half2float(h3));
                }
            }
        }
        return;
    }

#pragma unroll
    for (int mt = 0; mt < 2; mt++) {
        int row0 = bm + wm + mt * 16 + (lane >> 2);
#pragma unroll
        for (int nt = 0; nt < 4; nt++) {
            int col0 = bn + wn + nt * 8 + (lane & 3) * 2;
            float b0 = 0.f, b1 = 0.f;
            if (bias) { b0 = bias[col0]; b1 = bias[col0 + 1]; }
            float o0 = acc[mt][nt][0] * ISCALE + b0;
            float o1 = acc[mt][nt][1] * ISCALE + b1;
            float o2 = acc[mt][nt][2] * ISCALE + b0;
            float o3 = acc[mt][nt][3] * ISCALE + b1;
            if (ACT == 1) {
                o0 = gelu_tanh(o0); o1 = gelu_tanh(o1);
                o2 = gelu_tanh(o2); o3 = gelu_tanh(o3);
            }
            if (OUTMODE & 1) {
                *(float2*)(Cf + (size_t)row0 * Nout + col0) = make_float2(o0, o1);
                *(float2*)(Cf + (size_t)(row0 + 8) * Nout + col0) = make_float2(o2, o3);
            }
            if (OUTMODE & 2) {
                __half h0 = __float2half(o0), h1 = __float2half(o1);
                __half h2 = __float2half(o2), h3 = __float2half(o3);
                *(uint32_t*)(Cp + (size_t)row0 * Nout + col0) =
                    (uint32_t)__half_as_ushort(h0) | ((uint32_t)__half_as_ushort(h1) << 16);
                *(uint32_t*)(Cp + cPstride + (size_t)row0 * Nout + col0) =
                    packh(o0 - __half2float(h0), o1 - __half2float(h1));
                *(uint32_t*)(Cp + (size_t)(row0 + 8) * Nout + col0) =
                    (uint32_t)__half_as_ushort(h2) | ((uint32_t)__half_as_ushort(h3) << 16);
                *(uint32_t*)(Cp + cPstride + (size_t)(row0 + 8) * Nout + col0) =
                    packh(o2 - __half2float(h2), o3 - __half2float(h3));
            }
            if (OUTMODE & 4) {
                *(uint32_t*)(Cp + (size_t)row0 * Nout + col0) = packh(o0, o1);
                *(uint32_t*)(Cp + (size_t)(row0 + 8) * Nout + col0) = packh(o2, o3);
            }
        }
    }
}

// ---------------- input split: src+tgt fp32 -> 2 fp16 planes ----------------
__global__ void insplit(const float4* __restrict__ src4, const float4* __restrict__ tgt4,
                        __half* __restrict__ out)
{
    size_t i = (size_t)blockIdx.x * 256 + threadIdx.x;
    const size_t half4 = (size_t)MROWS * 256;
    float4 f = (i < half4) ? src4[i] : tgt4[i - half4];
    float v[4] = {f.x, f.y, f.z, f.w};
    uint32_t hp[2], lp[2];
#pragma unroll
    for (int j = 0; j < 2; j++) {
        __half h0 = __float2half(v[2 * j]), h1 = __float2half(v[2 * j + 1]);
        hp[j] = (uint32_t)__half_as_ushort(h0) | ((uint32_t)__half_as_ushort(h1) << 16);
        lp[j] = packh(v[2 * j] - __half2float(h0), v[2 * j + 1] - __half2float(h1));
    }
    *(uint2*)(out + 4 * i) = make_uint2(hp[0], hp[1]);
    *(uint2*)(out + PSIN + 4 * i) = make_uint2(lp[0], lp[1]);
}

// ---------------- weight prep ----------------
__global__ void split_kernel(const float* __restrict__ W, __half* __restrict__ out,
                             int n, int pstride)
{
    int i = blockIdx.x * 256 + threadIdx.x;
    if (i >= n) return;
    float r = W[i] * WSCALE;
    __half h = __float2half(r);
    out[i] = h;
    r -= __half2float(h);
    out[(size_t)pstride + i] = __float2half(r);
}

__global__ void swab_split(const float* __restrict__ Wa, const float* __restrict__ Wb,
                           __half* __restrict__ out)
{
    int i = blockIdx.x * 256 + threadIdx.x;   // 262144
    int nrow = i >> 8, k = i & 255;
    int j = nrow >> 6, r = nrow & 63;
    float w = (r < 32) ? Wa[(j * 32 + r) * 256 + k] : Wb[(j * 32 + r - 32) * 256 + k];
    float rr = w * WSCALE;
    __half h = __float2half(rr);
    out[i] = h;
    rr -= __half2float(h);
    out[262144 + i] = __float2half(rr);
}

__global__ void tsplit_kernel(const float* __restrict__ W, __half* __restrict__ out)
{
    int i = blockIdx.x * 256 + threadIdx.x;
    int nrow = i >> 8, k = i & 255;
    float r = W[k * 256 + nrow] * WSCALE;
    __half h = __float2half(r);
    out[i] = h;
    r -= __half2float(h);
    out[65536 + i] = __float2half(r);
}

__global__ void fusew_kernel(const float* __restrict__ W2, const float* __restrict__ Wc,
                             float* __restrict__ Wf)
{
    int idx = blockIdx.x * blockDim.x + threadIdx.x;
    int i = idx >> 9, j = idx & 511;
    float s = 0.0f;
    for (int k = 0; k < 256; k++) s += W2[i * 256 + k] * Wc[k * 512 + j];
    Wf[idx] = s;
}

// ---------------- elementwise ----------------
template <int NC>
__global__ void rmsnorm_kernel(float* __restrict__ x, const float* __restrict__ g, int rows)
{
    int row = blockIdx.x * 8 + (threadIdx.x >> 5);
    int lane = threadIdx.x & 31;
    if (row >= rows) return;
    float* p = x + (size_t)row * NC;
    constexpr int V = NC / 32;
    float v[V];
    float ss = 0.0f;
#pragma unroll
    for (int i = 0; i < V; i++) { v[i] = p[lane + 32 * i]; ss += v[i] * v[i]; }
#pragma unroll
    for (int o = 16; o > 0; o >>= 1) ss += __shfl_xor_sync(0xffffffffu, ss, o);
    float sc = rsqrtf(ss * (1.0f / NC) + 1e-6f);
#pragma unroll
    for (int i = 0; i < V; i++) p[lane + 32 * i] = v[i] * sc * g[lane + 32 * i];
}

// rmsnorm reading fp32, writing fp16 planes (N=256)
__global__ void rmsnorm_planes(const float* __restrict__ x, const float* __restrict__ g,
                               __half* __restrict__ out, int rows)
{
    int row = blockIdx.x * 8 + (threadIdx.x >> 5);
    int lane = threadIdx.x & 31;
    if (row >= rows) return;
    const float* p = x + (size_t)row * 256;
    float v[8];
    float ss = 0.0f;
#pragma unroll
    for (int i = 0; i < 8; i++) { v[i] = p[lane + 32 * i]; ss += v[i] * v[i]; }
#pragma unroll
    for (int o = 16; o > 0; o >>= 1) ss += __shfl_xor_sync(0xffffffffu, ss, o);
    float sc = rsqrtf(ss * (1.0f / 256.0f) + 1e-6f);
#pragma unroll
    for (int i = 0; i < 8; i++) {
        float o = v[i] * sc * g[lane + 32 * i];
        __half h = __float2half(o);
        out[(size_t)row * 256 + lane + 32 * i] = h;
        out[PX1 + (size_t)row * 256 + lane + 32 * i] = __float2half(o - __half2float(h));
    }
}

// ---------------- per-batch sinkhorn etc ----------------
__global__ __launch_bounds__(256) void batch_kernel(
    const float* __restrict__ u, const float* __restrict__ tgt,
    const float* __restrict__ src, const float* __restrict__ bbil,
    const float* __restrict__ Wc1, const float* __restrict__ bc1,
    float* __restrict__ out_mapping, float* __restrict__ out_mapped,
    float* __restrict__ out_conf, __half* __restrict__ combP)
{
    const int b = blockIdx.x;
    const int tid = threadIdx.x;
    __shared__ float u_s[RROLE * HDIM];
    __shared__ float t_s[RROLE * HDIM];
    __shared__ float s_s[RROLE * HDIM];
    __shared__ float la[RROLE * RROLE];
    __shared__ float map_s[RROLE * RROLE];
    __shared__ float lse[RROLE];
    __shared__ float red[256];

    const size_t base = (size_t)b * RROLE * HDIM;
    for (int e = tid; e < RROLE * HDIM; e += 256) {
        u_s[e] = u[base + e];
        t_s[e] = tgt[base + e];
        s_s[e] = src[base + e];
    }
    __syncthreads();

    const float bb = bbil[0];
    const int warp = tid >> 5, lane = tid & 31;
    for (int p = warp; p < RROLE * RROLE; p += 8) {
        int i = p / RROLE, j = p % RROLE;
        float d = 0.0f;
        for (int h = lane; h < HDIM; h += 32) d += u_s[i * HDIM + h] * t_s[j * HDIM + h];
#pragma unroll
        for (int o = 16; o > 0; o >>= 1) d += __shfl_xor_sync(0xffffffffu, d, o);
        if (lane == 0) la[p] = (d + bb) * TEMP_INV;
    }
    __syncthreads();

    for (int it = 0; it < SINKHORN_ITERS; it++) {
        if (tid < RROLE) {
            float m = -1e30f;
            for (int j = 0; j < RROLE; j++) m = fmaxf(m, la[tid * RROLE + j]);
            float s = 0.0f;
            for (int j = 0; j < RROLE; j++) s += expf(la[tid * RROLE + j] - m);
            lse[tid] = m + logf(s);
        }
        __syncthreads();
        if (tid < RROLE * RROLE) la[tid] -= lse[tid / RROLE];
        __syncthreads();
        if (tid < RROLE) {
            float m = -1e30f;
            for (int i = 0; i < RROLE; i++) m = fmaxf(m, la[i * RROLE + tid]);
            float s = 0.0f;
            for (int i = 0; i < RROLE; i++) s += expf(la[i * RROLE + tid] - m);
            lse[tid] = m + logf(s);
        }
        __syncthreads();
        if (tid < RROLE * RROLE) la[tid] -= lse[tid % RROLE];
        __syncthreads();
    }

    if (tid < RROLE * RROLE) {
        float mv = expf(la[tid]);
        map_s[tid] = mv;
        out_mapping[(size_t)b * RROLE * RROLE + tid] = mv;
    }
    __syncthreads();

    float local = 0.0f;
    for (int e = tid; e < RROLE * HDIM; e += 256) {
        int i = e >> 8;
        int h = e & 255;
        float v = 0.0f;
#pragma unroll
        for (int j = 0; j < RROLE; j++) v += map_s[i * RROLE + j] * t_s[j * HDIM + h];
        out_mapped[base + e] = v;
        size_t cbase = ((size_t)b * RROLE + i) * 512;
        combP[cbase + h] = __float2half(v);
        combP[cbase + 256 + h] = __float2half(t_s[i * HDIM + h]);
        local += fabsf(v - s_s[e]);
    }
    red[tid] = local;
    __syncthreads();
    for (int s = 128; s > 0; s >>= 1) {
        if (tid < s) red[tid] += red[tid + s];
        __syncthreads();
    }
    if (tid == 0) {
        float conf_in = red[0] * (1.0f / (RROLE * HDIM));
        float z = conf_in * Wc1[0] + bc1[0];
        out_conf[b] = 1.0f / (1.0f + expf(-z));
    }
}

// ---------------- launch ----------------
#define SMEM3 92160
#define SMEM2 61440

extern "C" void kernel_launch(void* const* d_in, const int* in_sizes, int n_in,
                              void* d_out, int out_size)
{
    (void)in_sizes; (void)n_in; (void)out_size;
    const float* src  = (const float*)d_in[0];
    const float* tgt  = (const float*)d_in[1];
    const float* W1   = (const float*)d_in[2];
    const float* b1   = (const float*)d_in[3];
    const float* g1   = (const float*)d_in[4];
    const float* Wa   = (const float*)d_in[5];
    const float* Wb   = (const float*)d_in[6];
    const float* Wc   = (const float*)d_in[7];
    const float* W2   = (const float*)d_in[8];
    const float* b2   = (const float*)d_in[9];
    const float* Wbil = (const float*)d_in[10];
    const float* bbil = (const float*)d_in[11];
    const float* Wa1  = (const float*)d_in[12];
    const float* ba1  = (const float*)d_in[13];
    const float* Wa2  = (const float*)d_in[14];
    const float* ba2  = (const float*)d_in[15];
    const float* g2   = (const float*)d_in[16];
    const float* Wc1  = (const float*)d_in[17];
    const float* bc1  = (const float*)d_in[18];
    float* out = (float*)d_out;

    float *Wf, *x1, *enc, *ub;
    __half *inP, *x1P, *hP, *encP, *combP, *bigP;
    __half *W1P, *WabP, *WfP, *WbTP, *Wa1P, *Wa2P;
    cudaGetSymbolAddress((void**)&Wf,    g_Wf);
    cudaGetSymbolAddress((void**)&x1,    g_x1);
    cudaGetSymbolAddress((void**)&enc,   g_enc);
    cudaGetSymbolAddress((void**)&ub,    g_u);
    cudaGetSymbolAddress((void**)&inP,   g_inP);
    cudaGetSymbolAddress((void**)&x1P,   g_x1P);
    cudaGetSymbolAddress((void**)&hP,    g_hP);
    cudaGetSymbolAddress((void**)&encP,  g_encP);
    cudaGetSymbolAddress((void**)&combP, g_combP);
    cudaGetSymbolAddress((void**)&bigP,  g_bigP);
    cudaGetSymbolAddress((void**)&W1P,   g_W1P);
    cudaGetSymbolAddress((void**)&WabP,  g_WabP);
    cudaGetSymbolAddress((void**)&WfP,   g_WfP);
    cudaGetSymbolAddress((void**)&WbTP,  g_WbTP);
    cudaGetSymbolAddress((void**)&Wa1P,  g_Wa1P);
    cudaGetSymbolAddress((void**)&Wa2P,  g_Wa2P);

    cudaFuncSetAttribute(gemm_mma<0,1,3>, cudaFuncAttributeMaxDynamicSharedMemorySize, SMEM3);
    cudaFuncSetAttribute(gemm_mma<0,3,3>, cudaFuncAttributeMaxDynamicSharedMemorySize, SMEM3);
    cudaFuncSetAttribute(gemm_mma<2,2,3>, cudaFuncAttributeMaxDynamicSharedMemorySize, SMEM3);
    cudaFuncSetAttribute(gemm_mma<1,4,2>, cudaFuncAttributeMaxDynamicSharedMemorySize, SMEM2);
    cudaFuncSetAttribute(gemm_mma<0,1,2>, cudaFuncAttributeMaxDynamicSharedMemorySize, SMEM2);

    // ---- prep ----
    fusew_kernel<<<512, 256>>>(W2, Wc, Wf);
    split_kernel<<<1024, 256>>>(W1, W1P, 262144, 262144);
    swab_split<<<1024, 256>>>(Wa, Wb, WabP);
    split_kernel<<<512, 256>>>(Wf, WfP, 131072, 131072);
    tsplit_kernel<<<256, 256>>>(Wbil, WbTP);
    split_kernel<<<1024, 256>>>(Wa1, Wa1P, 262144, 262144);
    split_kernel<<<2048, 256>>>(Wa2, Wa2P, 524288, 524288);
    insplit<<<M2 * 256 / 256, 256>>>((const float4*)src, (const float4*)tgt, inP);

    // ---- merged encoder (src rows 0..M-1, tgt rows M..2M-1) ----
    gemm_mma<0,1,3><<<dim3(4, M2 / 128), 256, SMEM3>>>(
        inP, PSIN, W1P, 262144, b1, x1, nullptr, 0, 256, 1024, 256);
    rmsnorm_planes<<<M2 / 8, 256>>>(x1, g1, x1P, M2);
    gemm_mma<2,2,3><<<dim3(16, M2 / 128), 256, SMEM3>>>(
        x1P, PX1, WabP, 262144, nullptr, nullptr, hP, PH, 1024, 256, 512);
    gemm_mma<0,3,3><<<dim3(4, M2 / 128), 256, SMEM3>>>(
        hP, PH, WfP, 131072, b2, enc, encP, PE, 256, 512, 256);

    // ---- bilinear u = enc_src @ Wbil (first MROWS rows of encP) ----
    gemm_mma<0,1,3><<<dim3(4, MROWS / 128), 256, SMEM3>>>(
        encP, PE, WbTP, 65536, nullptr, ub, nullptr, 0, 256, 256, 256);

    // ---- sinkhorn / mapping / confidence / combined (hi plane only) ----
    batch_kernel<<<BATCH, 256>>>(ub, enc + (size_t)MROWS * 256, enc, bbil, Wc1, bc1,
                                 out + OUT_MAPPING_OFF, out + OUT_MAPPED_OFF,
                                 out + OUT_CONF_OFF, combP);

    // ---- answer projection (2-product path) ----
    gemm_mma<1,4,2><<<dim3(8, MROWS / 128), 256, SMEM2>>>(
        combP, 0, Wa1P, 262144, ba1, nullptr, bigP, 0, 512, 512, 512);
    gemm_mma<0,1,2><<<dim3(16, MROWS / 128), 256, SMEM2>>>(
        bigP, 0, Wa2P, 524288, ba2, out + OUT_ANSWER_OFF, nullptr, 0, 1024, 512, 1024);
    rmsnorm_kernel<DDIM><<<MROWS / 8, 256>>>(out + OUT_ANSWER_OFF, g2, MROWS);
}